// round 1
// baseline (speedup 1.0000x reference)
#include <cuda_runtime.h>
#include <math.h>

#define BB  4
#define TT  2048
#define CC  1024
#define HH  16
#define DD  64
#define WFF 4096
#define MM  (BB*TT)   // 8192

// ---------------- scratch (device globals: allocation-free) ----------------
__device__ float g_h [(size_t)MM*CC];
__device__ float g_q [(size_t)MM*CC];
__device__ float g_k [(size_t)MM*CC];
__device__ float g_v [(size_t)MM*CC];
__device__ float g_y [(size_t)MM*CC];
__device__ float g_x2[(size_t)MM*CC];
__device__ float g_ff[(size_t)MM*WFF];

// ---------------- LayerNorm: one block (256 thr) per row of 1024 ----------
__global__ void __launch_bounds__(256) ln_kernel(
    const float* __restrict__ X, const float* __restrict__ gw,
    const float* __restrict__ gb, float* __restrict__ O) {
    __shared__ float red[16];
    int row = blockIdx.x;
    int t = threadIdx.x;
    const float* xr = X + (size_t)row * CC;
    float4 v = *(const float4*)(xr + t * 4);
    float s  = v.x + v.y + v.z + v.w;
    float ss = v.x*v.x + v.y*v.y + v.z*v.z + v.w*v.w;
#pragma unroll
    for (int o = 16; o; o >>= 1) {
        s  += __shfl_down_sync(0xffffffffu, s,  o);
        ss += __shfl_down_sync(0xffffffffu, ss, o);
    }
    if ((t & 31) == 0) { red[t >> 5] = s; red[8 + (t >> 5)] = ss; }
    __syncthreads();
    if (t == 0) {
        float a = 0.f, c = 0.f;
#pragma unroll
        for (int i = 0; i < 8; i++) { a += red[i]; c += red[8 + i]; }
        float mean = a * (1.f / CC);
        float var  = c * (1.f / CC) - mean * mean;
        red[0] = mean;
        red[1] = rsqrtf(var + 1e-5f);
    }
    __syncthreads();
    float mean = red[0], rstd = red[1];
    float4 w4 = *(const float4*)(gw + t * 4);
    float4 b4 = *(const float4*)(gb + t * 4);
    float4 r;
    r.x = (v.x - mean) * rstd * w4.x + b4.x;
    r.y = (v.y - mean) * rstd * w4.y + b4.y;
    r.z = (v.z - mean) * rstd * w4.z + b4.z;
    r.w = (v.w - mean) * rstd * w4.w + b4.w;
    *(float4*)(O + (size_t)row * CC + t * 4) = r;
}

// ---------------- SGEMM 128x128x8, 256 thr, 8x8 microtile ------------------
// EPI: 0 = bias, 1 = bias+relu, 2 = bias+residual
template <int EPI>
__global__ void __launch_bounds__(256) sgemm_kernel(
    const float* __restrict__ A, const float* __restrict__ Bw,
    const float* __restrict__ bias, const float* __restrict__ res,
    float* __restrict__ Cout, int M, int N, int K) {
    __shared__ float As[8][128];
    __shared__ float Bs[8][128];
    int bm = blockIdx.y << 7;
    int bn = blockIdx.x << 7;
    int tid = threadIdx.x;
    int arow = tid >> 1, acol = (tid & 1) << 2;
    int brow = tid >> 5, bcol = (tid & 31) << 2;
    int tx = tid & 15, ty = tid >> 4;
    const float* Aptr = A  + (size_t)(bm + arow) * K + acol;
    const float* Bptr = Bw + (size_t)brow * N + bn + bcol;

    float acc[8][8];
#pragma unroll
    for (int i = 0; i < 8; i++)
#pragma unroll
        for (int j = 0; j < 8; j++) acc[i][j] = 0.f;

    for (int k0 = 0; k0 < K; k0 += 8) {
        float4 a4 = *(const float4*)(Aptr + k0);
        As[acol + 0][arow] = a4.x;
        As[acol + 1][arow] = a4.y;
        As[acol + 2][arow] = a4.z;
        As[acol + 3][arow] = a4.w;
        float4 b4 = *(const float4*)(Bptr + (size_t)k0 * N);
        *(float4*)&Bs[brow][bcol] = b4;
        __syncthreads();
#pragma unroll
        for (int kk = 0; kk < 8; kk++) {
            float a[8], bv[8];
            *(float4*)&a[0]  = *(const float4*)&As[kk][ty * 8];
            *(float4*)&a[4]  = *(const float4*)&As[kk][ty * 8 + 4];
            *(float4*)&bv[0] = *(const float4*)&Bs[kk][tx * 8];
            *(float4*)&bv[4] = *(const float4*)&Bs[kk][tx * 8 + 4];
#pragma unroll
            for (int i = 0; i < 8; i++)
#pragma unroll
                for (int j = 0; j < 8; j++) acc[i][j] += a[i] * bv[j];
        }
        __syncthreads();
    }
#pragma unroll
    for (int i = 0; i < 8; i++) {
        int row = bm + ty * 8 + i;
#pragma unroll
        for (int j = 0; j < 8; j += 4) {
            int col = bn + tx * 8 + j;
            float4 bv = *(const float4*)(bias + col);
            float4 o;
            o.x = acc[i][j + 0] + bv.x;
            o.y = acc[i][j + 1] + bv.y;
            o.z = acc[i][j + 2] + bv.z;
            o.w = acc[i][j + 3] + bv.w;
            if (EPI == 1) {
                o.x = fmaxf(o.x, 0.f); o.y = fmaxf(o.y, 0.f);
                o.z = fmaxf(o.z, 0.f); o.w = fmaxf(o.w, 0.f);
            }
            if (EPI == 2) {
                float4 rr = *(const float4*)(res + (size_t)row * N + col);
                o.x += rr.x; o.y += rr.y; o.z += rr.z; o.w += rr.w;
            }
            *(float4*)(Cout + (size_t)row * N + col) = o;
        }
    }
}

// ---------------- Flash attention fp32: BQ=BK=64, D=64 ---------------------
#define APAD 68
#define SMEM_ATTN (4 * 64 * APAD * 4)

__global__ void __launch_bounds__(256) attn_kernel(
    const float* __restrict__ Q, const float* __restrict__ K,
    const float* __restrict__ V, float* __restrict__ Y) {
    extern __shared__ float sm[];
    float* Qs = sm;
    float* Ks = Qs + 64 * APAD;
    float* Vs = Ks + 64 * APAD;
    float* Ps = Vs + 64 * APAD;

    int qt = blockIdx.x, hh = blockIdx.y, b = blockIdx.z;
    int tid = threadIdx.x;
    int tx = tid & 15, ty = tid >> 4;
    const size_t base = ((size_t)b * TT) * CC + hh * DD;

    int lr = tid >> 4, lc = (tid & 15) << 2;
#pragma unroll
    for (int it = 0; it < 4; it++) {
        int row = lr + it * 16;
        *(float4*)&Qs[row * APAD + lc] =
            *(const float4*)(Q + base + (size_t)(qt * 64 + row) * CC + lc);
    }

    float m_i[4], l_i[4], o[4][4];
#pragma unroll
    for (int i = 0; i < 4; i++) {
        m_i[i] = -1e30f; l_i[i] = 0.f;
#pragma unroll
        for (int j = 0; j < 4; j++) o[i][j] = 0.f;
    }

    for (int kt = 0; kt <= qt; kt++) {
        __syncthreads();
#pragma unroll
        for (int it = 0; it < 4; it++) {
            int row = lr + it * 16;
            *(float4*)&Ks[row * APAD + lc] =
                *(const float4*)(K + base + (size_t)(kt * 64 + row) * CC + lc);
            *(float4*)&Vs[row * APAD + lc] =
                *(const float4*)(V + base + (size_t)(kt * 64 + row) * CC + lc);
        }
        __syncthreads();

        float s[4][4];
#pragma unroll
        for (int i = 0; i < 4; i++)
#pragma unroll
            for (int j = 0; j < 4; j++) s[i][j] = 0.f;

#pragma unroll
        for (int d4 = 0; d4 < 16; d4++) {
            float4 qv[4], kv[4];
#pragma unroll
            for (int i = 0; i < 4; i++)
                qv[i] = *(const float4*)&Qs[(ty * 4 + i) * APAD + d4 * 4];
#pragma unroll
            for (int j = 0; j < 4; j++)
                kv[j] = *(const float4*)&Ks[(tx * 4 + j) * APAD + d4 * 4];
#pragma unroll
            for (int i = 0; i < 4; i++)
#pragma unroll
                for (int j = 0; j < 4; j++)
                    s[i][j] += qv[i].x * kv[j].x + qv[i].y * kv[j].y +
                               qv[i].z * kv[j].z + qv[i].w * kv[j].w;
        }

        bool diag = (kt == qt);
#pragma unroll
        for (int i = 0; i < 4; i++) {
#pragma unroll
            for (int j = 0; j < 4; j++) {
                float sv = s[i][j] * 0.125f;   // 1/sqrt(64)
                if (diag && (tx * 4 + j > ty * 4 + i)) sv = -1e30f;
                s[i][j] = sv;
            }
            float rm = fmaxf(fmaxf(s[i][0], s[i][1]), fmaxf(s[i][2], s[i][3]));
#pragma unroll
            for (int off = 8; off; off >>= 1)
                rm = fmaxf(rm, __shfl_xor_sync(0xffffffffu, rm, off));
            float mnew = fmaxf(m_i[i], rm);
            float alpha = __expf(m_i[i] - mnew);
            m_i[i] = mnew;
            float rs = 0.f;
#pragma unroll
            for (int j = 0; j < 4; j++) {
                s[i][j] = __expf(s[i][j] - mnew);
                rs += s[i][j];
            }
#pragma unroll
            for (int off = 8; off; off >>= 1)
                rs += __shfl_xor_sync(0xffffffffu, rs, off);
            l_i[i] = l_i[i] * alpha + rs;
#pragma unroll
            for (int j = 0; j < 4; j++) o[i][j] *= alpha;
            *(float4*)&Ps[(ty * 4 + i) * APAD + tx * 4] =
                make_float4(s[i][0], s[i][1], s[i][2], s[i][3]);
        }
        __syncthreads();

#pragma unroll
        for (int k4 = 0; k4 < 16; k4++) {
            float pr[4][4], vr[4][4];
#pragma unroll
            for (int i = 0; i < 4; i++) {
                float4 t = *(const float4*)&Ps[(ty * 4 + i) * APAD + k4 * 4];
                pr[i][0] = t.x; pr[i][1] = t.y; pr[i][2] = t.z; pr[i][3] = t.w;
            }
#pragma unroll
            for (int kk = 0; kk < 4; kk++) {
                float4 t = *(const float4*)&Vs[(k4 * 4 + kk) * APAD + tx * 4];
                vr[kk][0] = t.x; vr[kk][1] = t.y; vr[kk][2] = t.z; vr[kk][3] = t.w;
            }
#pragma unroll
            for (int i = 0; i < 4; i++)
#pragma unroll
                for (int j = 0; j < 4; j++)
#pragma unroll
                    for (int kk = 0; kk < 4; kk++)
                        o[i][j] += pr[i][kk] * vr[kk][j];
        }
    }

#pragma unroll
    for (int i = 0; i < 4; i++) {
        float inv = 1.f / l_i[i];
        int qg = qt * 64 + ty * 4 + i;
        float4 ov = make_float4(o[i][0] * inv, o[i][1] * inv,
                                o[i][2] * inv, o[i][3] * inv);
        *(float4*)(Y + base + (size_t)qg * CC + tx * 4) = ov;
    }
}

// ---------------- launch ---------------------------------------------------
extern "C" void kernel_launch(void* const* d_in, const int* in_sizes, int n_in,
                              void* d_out, int out_size) {
    const float* x    = (const float*)d_in[0];
    const float* ln1w = (const float*)d_in[1];
    const float* ln1b = (const float*)d_in[2];
    const float* Wq   = (const float*)d_in[3];
    const float* bq   = (const float*)d_in[4];
    const float* Wk   = (const float*)d_in[5];
    const float* bk   = (const float*)d_in[6];
    const float* Wv   = (const float*)d_in[7];
    const float* bv   = (const float*)d_in[8];
    const float* Wo   = (const float*)d_in[9];
    const float* bo   = (const float*)d_in[10];
    const float* ln2w = (const float*)d_in[11];
    const float* ln2b = (const float*)d_in[12];
    const float* W1   = (const float*)d_in[13];
    const float* b1   = (const float*)d_in[14];
    const float* W2   = (const float*)d_in[15];
    const float* b2   = (const float*)d_in[16];
    float* out = (float*)d_out;

    float *h, *q, *k, *v, *y, *x2, *ff;
    cudaGetSymbolAddress((void**)&h,  g_h);
    cudaGetSymbolAddress((void**)&q,  g_q);
    cudaGetSymbolAddress((void**)&k,  g_k);
    cudaGetSymbolAddress((void**)&v,  g_v);
    cudaGetSymbolAddress((void**)&y,  g_y);
    cudaGetSymbolAddress((void**)&x2, g_x2);
    cudaGetSymbolAddress((void**)&ff, g_ff);

    cudaFuncSetAttribute(attn_kernel,
                         cudaFuncAttributeMaxDynamicSharedMemorySize, SMEM_ATTN);

    // LN1
    ln_kernel<<<MM, 256>>>(x, ln1w, ln1b, h);
    // QKV projections
    dim3 g1(CC / 128, MM / 128);
    sgemm_kernel<0><<<g1, 256>>>(h, Wq, bq, nullptr, q, MM, CC, CC);
    sgemm_kernel<0><<<g1, 256>>>(h, Wk, bk, nullptr, k, MM, CC, CC);
    sgemm_kernel<0><<<g1, 256>>>(h, Wv, bv, nullptr, v, MM, CC, CC);
    // causal attention
    attn_kernel<<<dim3(TT / 64, HH, BB), 256, SMEM_ATTN>>>(q, k, v, y);
    // output projection + residual
    sgemm_kernel<2><<<g1, 256>>>(y, Wo, bo, x, x2, MM, CC, CC);
    // LN2
    ln_kernel<<<MM, 256>>>(x2, ln2w, ln2b, h);
    // FF1 (relu)
    dim3 g2(WFF / 128, MM / 128);
    sgemm_kernel<1><<<g2, 256>>>(h, W1, b1, nullptr, ff, MM, WFF, CC);
    // FF2 + residual -> out
    sgemm_kernel<2><<<g1, 256>>>(ff, W2, b2, x2, out, MM, CC, WFF);
}

// round 3
// speedup vs baseline: 2.2628x; 2.2628x over previous
#include <cuda_runtime.h>
#include <cstdint>
#include <math.h>

#define BB  4
#define TT  2048
#define CC  1024
#define HH  16
#define DD  64
#define WFF 4096
#define MM  (BB*TT)   // 8192

// ---------------- scratch (device globals: allocation-free) ----------------
__device__ float g_h [(size_t)MM*CC];
__device__ float g_q [(size_t)MM*CC];
__device__ float g_k [(size_t)MM*CC];
__device__ float g_v [(size_t)MM*CC];
__device__ float g_y [(size_t)MM*CC];
__device__ float g_x2[(size_t)MM*CC];
__device__ float g_ff[(size_t)MM*WFF];
__device__ float g_wT[(size_t)4*CC*CC + (size_t)2*CC*WFF];

// ---------------- helpers ----------------------------------------------------
__device__ __forceinline__ uint32_t smem_u32(const void* p) {
    uint32_t a;
    asm("{ .reg .u64 t; cvta.to.shared.u64 t, %1; cvt.u32.u64 %0, t; }"
        : "=r"(a) : "l"(p));
    return a;
}
__device__ __forceinline__ void cp16(uint32_t s, const void* g) {
    asm volatile("cp.async.cg.shared.global [%0], [%1], 16;"
                 :: "r"(s), "l"(g) : "memory");
}
#define CP_COMMIT() asm volatile("cp.async.commit_group;" ::: "memory")
#define CP_WAIT0()  asm volatile("cp.async.wait_group 0;" ::: "memory")
#define CP_WAIT1()  asm volatile("cp.async.wait_group 1;" ::: "memory")

__device__ __forceinline__ void mma_tf32(float* c, const uint32_t* a,
                                         const uint32_t* b) {
    asm volatile(
        "mma.sync.aligned.m16n8k8.row.col.f32.tf32.tf32.f32 "
        "{%0,%1,%2,%3}, {%4,%5,%6,%7}, {%8,%9}, {%0,%1,%2,%3};"
        : "+f"(c[0]), "+f"(c[1]), "+f"(c[2]), "+f"(c[3])
        : "r"(a[0]), "r"(a[1]), "r"(a[2]), "r"(a[3]),
          "r"(b[0]), "r"(b[1]));
}

// ---------------- weight transpose: dst[n,r] = src[r,n] ---------------------
__global__ void __launch_bounds__(256) transpose_kernel(
    const float* __restrict__ src, float* __restrict__ dst, int R, int Ncols) {
    __shared__ float t[32][33];
    int bx = blockIdx.x * 32, by = blockIdx.y * 32;
    int tx = threadIdx.x, ty = threadIdx.y;
#pragma unroll
    for (int i = 0; i < 32; i += 8)
        t[ty + i][tx] = src[(size_t)(by + ty + i) * Ncols + bx + tx];
    __syncthreads();
#pragma unroll
    for (int i = 0; i < 32; i += 8)
        dst[(size_t)(bx + ty + i) * R + by + tx] = t[tx][ty + i];
}

// ---------------- LayerNorm --------------------------------------------------
__global__ void __launch_bounds__(256) ln_kernel(
    const float* __restrict__ X, const float* __restrict__ gw,
    const float* __restrict__ gb, float* __restrict__ O) {
    __shared__ float red[16];
    int row = blockIdx.x;
    int t = threadIdx.x;
    const float* xr = X + (size_t)row * CC;
    float4 v = *(const float4*)(xr + t * 4);
    float s  = v.x + v.y + v.z + v.w;
    float ss = v.x*v.x + v.y*v.y + v.z*v.z + v.w*v.w;
#pragma unroll
    for (int o = 16; o; o >>= 1) {
        s  += __shfl_down_sync(0xffffffffu, s,  o);
        ss += __shfl_down_sync(0xffffffffu, ss, o);
    }
    if ((t & 31) == 0) { red[t >> 5] = s; red[8 + (t >> 5)] = ss; }
    __syncthreads();
    if (t == 0) {
        float a = 0.f, c = 0.f;
#pragma unroll
        for (int i = 0; i < 8; i++) { a += red[i]; c += red[8 + i]; }
        float mean = a * (1.f / CC);
        float var  = c * (1.f / CC) - mean * mean;
        red[0] = mean;
        red[1] = rsqrtf(var + 1e-5f);
    }
    __syncthreads();
    float mean = red[0], rstd = red[1];
    float4 w4 = *(const float4*)(gw + t * 4);
    float4 b4 = *(const float4*)(gb + t * 4);
    float4 r;
    r.x = (v.x - mean) * rstd * w4.x + b4.x;
    r.y = (v.y - mean) * rstd * w4.y + b4.y;
    r.z = (v.z - mean) * rstd * w4.z + b4.z;
    r.w = (v.w - mean) * rstd * w4.w + b4.w;
    *(float4*)(O + (size_t)row * CC + t * 4) = r;
}

// ---------------- tf32 mma.sync GEMM: tile 128x128, BK=32 -------------------
// A: [M,K] row-major.  Bt: [N,K] row-major (pre-transposed weights).
// EPI: 0 = bias, 1 = bias+relu, 2 = bias+residual
#define GSMEM_BYTES 65536   // 2 bufs x (A 16KB + B 16KB)

template <int EPI>
__global__ void __launch_bounds__(256, 2) gemm_mma(
    const float* __restrict__ A, const float* __restrict__ Bt,
    const float* __restrict__ bias, const float* __restrict__ res,
    float* __restrict__ Cout, int M, int N, int K) {
    extern __shared__ float sm[];
    int tid = threadIdx.x;
    int wid = tid >> 5, lane = tid & 31;
    int gid = lane >> 2, tig = lane & 3;
    int wm = wid >> 1, wn = wid & 1;
    int bm = blockIdx.y << 7, bn = blockIdx.x << 7;

    const float* Ag = A  + (size_t)bm * K;
    const float* Bg = Bt + (size_t)bn * K;
    uint32_t smb = smem_u32(sm);

    // ---- chunk loader: 128x32 floats each for A and B, XOR-swizzled --------
    auto load_chunk = [&](int c, int b) {
        const float* Ac = Ag + c * 32;
        const float* Bc = Bg + c * 32;
        uint32_t ab = smb + b * 32768;
        uint32_t bb = ab + 16384;
#pragma unroll
        for (int i = 0; i < 4; i++) {
            int idx = tid + (i << 8);
            int row = idx >> 3, c4 = idx & 7;
            uint32_t off = (uint32_t)(row * 128 + ((c4 * 16) ^ ((row & 7) * 16)));
            const float* ga = Ac + (size_t)row * K + c4 * 4;
            const float* gb = Bc + (size_t)row * K + c4 * 4;
            cp16(ab + off, ga);
            cp16(bb + off, gb);
        }
    };

    float acc[2][8][4];
#pragma unroll
    for (int mt = 0; mt < 2; mt++)
#pragma unroll
        for (int nt = 0; nt < 8; nt++)
#pragma unroll
            for (int r = 0; r < 4; r++) acc[mt][nt][r] = 0.f;

    int nc = K >> 5;
    load_chunk(0, 0);
    CP_COMMIT();

    for (int c = 0; c < nc; c++) {
        int b = c & 1;
        if (c + 1 < nc) {
            load_chunk(c + 1, b ^ 1);
            CP_COMMIT();
            CP_WAIT1();
        } else {
            CP_WAIT0();
        }
        __syncthreads();

        const float* sAb = sm + b * 8192;
        const float* sBb = sAb + 4096;
#pragma unroll
        for (int ks = 0; ks < 4; ks++) {
            int k0 = ks * 8 + tig;
            uint32_t aF[2][4], bF[8][2];
#pragma unroll
            for (int mt = 0; mt < 2; mt++) {
                int r0 = wm * 32 + mt * 16 + gid;
                const float* pa = sAb + r0 * 32;
                int sw = (r0 & 7) * 4;
                aF[mt][0] = __float_as_uint(pa[k0 ^ sw]);
                aF[mt][1] = __float_as_uint(pa[256 + (k0 ^ sw)]);
                aF[mt][2] = __float_as_uint(pa[(k0 + 4) ^ sw]);
                aF[mt][3] = __float_as_uint(pa[256 + ((k0 + 4) ^ sw)]);
            }
#pragma unroll
            for (int nt = 0; nt < 8; nt++) {
                int n0 = wn * 64 + nt * 8 + gid;
                const float* pb = sBb + n0 * 32;
                int sw = (n0 & 7) * 4;
                bF[nt][0] = __float_as_uint(pb[k0 ^ sw]);
                bF[nt][1] = __float_as_uint(pb[(k0 + 4) ^ sw]);
            }
#pragma unroll
            for (int mt = 0; mt < 2; mt++)
#pragma unroll
                for (int nt = 0; nt < 8; nt++)
                    mma_tf32(acc[mt][nt], aF[mt], bF[nt]);
        }
        __syncthreads();
    }

    // ---- epilogue: direct stores with fused bias/relu/residual -------------
#pragma unroll
    for (int mt = 0; mt < 2; mt++) {
        int r0 = bm + wm * 32 + mt * 16 + gid;
#pragma unroll
        for (int half = 0; half < 2; half++) {
            int row = r0 + half * 8;
#pragma unroll
            for (int nt = 0; nt < 8; nt++) {
                int col = bn + wn * 64 + nt * 8 + tig * 2;
                float2 bv = *(const float2*)(bias + col);
                float2 o;
                o.x = acc[mt][nt][half * 2 + 0] + bv.x;
                o.y = acc[mt][nt][half * 2 + 1] + bv.y;
                if (EPI == 1) {
                    o.x = fmaxf(o.x, 0.f);
                    o.y = fmaxf(o.y, 0.f);
                }
                if (EPI == 2) {
                    float2 rr = *(const float2*)(res + (size_t)row * N + col);
                    o.x += rr.x; o.y += rr.y;
                }
                *(float2*)(Cout + (size_t)row * N + col) = o;
            }
        }
    }
}

// ---------------- Flash attention fp32: BQ=BK=64, D=64 ---------------------
#define APAD 68
#define SMEM_ATTN (4 * 64 * APAD * 4)

__global__ void __launch_bounds__(256) attn_kernel(
    const float* __restrict__ Q, const float* __restrict__ K,
    const float* __restrict__ V, float* __restrict__ Y) {
    extern __shared__ float sm[];
    float* Qs = sm;
    float* Ks = Qs + 64 * APAD;
    float* Vs = Ks + 64 * APAD;
    float* Ps = Vs + 64 * APAD;

    int qt = blockIdx.x, hh = blockIdx.y, b = blockIdx.z;
    int tid = threadIdx.x;
    int tx = tid & 15, ty = tid >> 4;
    const size_t base = ((size_t)b * TT) * CC + hh * DD;

    int lr = tid >> 4, lc = (tid & 15) << 2;
#pragma unroll
    for (int it = 0; it < 4; it++) {
        int row = lr + it * 16;
        *(float4*)&Qs[row * APAD + lc] =
            *(const float4*)(Q + base + (size_t)(qt * 64 + row) * CC + lc);
    }

    float m_i[4], l_i[4], o[4][4];
#pragma unroll
    for (int i = 0; i < 4; i++) {
        m_i[i] = -1e30f; l_i[i] = 0.f;
#pragma unroll
        for (int j = 0; j < 4; j++) o[i][j] = 0.f;
    }

    for (int kt = 0; kt <= qt; kt++) {
        __syncthreads();
#pragma unroll
        for (int it = 0; it < 4; it++) {
            int row = lr + it * 16;
            *(float4*)&Ks[row * APAD + lc] =
                *(const float4*)(K + base + (size_t)(kt * 64 + row) * CC + lc);
            *(float4*)&Vs[row * APAD + lc] =
                *(const float4*)(V + base + (size_t)(kt * 64 + row) * CC + lc);
        }
        __syncthreads();

        float s[4][4];
#pragma unroll
        for (int i = 0; i < 4; i++)
#pragma unroll
            for (int j = 0; j < 4; j++) s[i][j] = 0.f;

#pragma unroll
        for (int d4 = 0; d4 < 16; d4++) {
            float4 qv[4], kv[4];
#pragma unroll
            for (int i = 0; i < 4; i++)
                qv[i] = *(const float4*)&Qs[(ty * 4 + i) * APAD + d4 * 4];
#pragma unroll
            for (int j = 0; j < 4; j++)
                kv[j] = *(const float4*)&Ks[(tx * 4 + j) * APAD + d4 * 4];
#pragma unroll
            for (int i = 0; i < 4; i++)
#pragma unroll
                for (int j = 0; j < 4; j++)
                    s[i][j] += qv[i].x * kv[j].x + qv[i].y * kv[j].y +
                               qv[i].z * kv[j].z + qv[i].w * kv[j].w;
        }

        bool diag = (kt == qt);
#pragma unroll
        for (int i = 0; i < 4; i++) {
#pragma unroll
            for (int j = 0; j < 4; j++) {
                float sv = s[i][j] * 0.125f;
                if (diag && (tx * 4 + j > ty * 4 + i)) sv = -1e30f;
                s[i][j] = sv;
            }
            float rm = fmaxf(fmaxf(s[i][0], s[i][1]), fmaxf(s[i][2], s[i][3]));
#pragma unroll
            for (int off = 8; off; off >>= 1)
                rm = fmaxf(rm, __shfl_xor_sync(0xffffffffu, rm, off));
            float mnew = fmaxf(m_i[i], rm);
            float alpha = __expf(m_i[i] - mnew);
            m_i[i] = mnew;
            float rs = 0.f;
#pragma unroll
            for (int j = 0; j < 4; j++) {
                s[i][j] = __expf(s[i][j] - mnew);
                rs += s[i][j];
            }
#pragma unroll
            for (int off = 8; off; off >>= 1)
                rs += __shfl_xor_sync(0xffffffffu, rs, off);
            l_i[i] = l_i[i] * alpha + rs;
#pragma unroll
            for (int j = 0; j < 4; j++) o[i][j] *= alpha;
            *(float4*)&Ps[(ty * 4 + i) * APAD + tx * 4] =
                make_float4(s[i][0], s[i][1], s[i][2], s[i][3]);
        }
        __syncthreads();

#pragma unroll
        for (int k4 = 0; k4 < 16; k4++) {
            float pr[4][4], vr[4][4];
#pragma unroll
            for (int i = 0; i < 4; i++) {
                float4 t = *(const float4*)&Ps[(ty * 4 + i) * APAD + k4 * 4];
                pr[i][0] = t.x; pr[i][1] = t.y; pr[i][2] = t.z; pr[i][3] = t.w;
            }
#pragma unroll
            for (int kk = 0; kk < 4; kk++) {
                float4 t = *(const float4*)&Vs[(k4 * 4 + kk) * APAD + tx * 4];
                vr[kk][0] = t.x; vr[kk][1] = t.y; vr[kk][2] = t.z; vr[kk][3] = t.w;
            }
#pragma unroll
            for (int i = 0; i < 4; i++)
#pragma unroll
                for (int j = 0; j < 4; j++)
#pragma unroll
                    for (int kk = 0; kk < 4; kk++)
                        o[i][j] += pr[i][kk] * vr[kk][j];
        }
    }

#pragma unroll
    for (int i = 0; i < 4; i++) {
        float inv = 1.f / l_i[i];
        int qg = qt * 64 + ty * 4 + i;
        float4 ov = make_float4(o[i][0] * inv, o[i][1] * inv,
                                o[i][2] * inv, o[i][3] * inv);
        *(float4*)(Y + base + (size_t)qg * CC + tx * 4) = ov;
    }
}

// ---------------- launch ---------------------------------------------------
extern "C" void kernel_launch(void* const* d_in, const int* in_sizes, int n_in,
                              void* d_out, int out_size) {
    const float* x    = (const float*)d_in[0];
    const float* ln1w = (const float*)d_in[1];
    const float* ln1b = (const float*)d_in[2];
    const float* Wq   = (const float*)d_in[3];
    const float* bq   = (const float*)d_in[4];
    const float* Wk   = (const float*)d_in[5];
    const float* bk   = (const float*)d_in[6];
    const float* Wv   = (const float*)d_in[7];
    const float* bv   = (const float*)d_in[8];
    const float* Wo   = (const float*)d_in[9];
    const float* bo   = (const float*)d_in[10];
    const float* ln2w = (const float*)d_in[11];
    const float* ln2b = (const float*)d_in[12];
    const float* W1   = (const float*)d_in[13];
    const float* b1   = (const float*)d_in[14];
    const float* W2   = (const float*)d_in[15];
    const float* b2   = (const float*)d_in[16];
    float* out = (float*)d_out;

    float *h, *q, *k, *v, *y, *x2, *ff, *wT;
    cudaGetSymbolAddress((void**)&h,  g_h);
    cudaGetSymbolAddress((void**)&q,  g_q);
    cudaGetSymbolAddress((void**)&k,  g_k);
    cudaGetSymbolAddress((void**)&v,  g_v);
    cudaGetSymbolAddress((void**)&y,  g_y);
    cudaGetSymbolAddress((void**)&x2, g_x2);
    cudaGetSymbolAddress((void**)&ff, g_ff);
    cudaGetSymbolAddress((void**)&wT, g_wT);

    float* WqT = wT;
    float* WkT = WqT + (size_t)CC * CC;
    float* WvT = WkT + (size_t)CC * CC;
    float* WoT = WvT + (size_t)CC * CC;
    float* W1T = WoT + (size_t)CC * CC;          // [WFF, CC]
    float* W2T = W1T + (size_t)CC * WFF;         // [CC, WFF]

    cudaFuncSetAttribute(attn_kernel,
                         cudaFuncAttributeMaxDynamicSharedMemorySize, SMEM_ATTN);
    cudaFuncSetAttribute(gemm_mma<0>,
                         cudaFuncAttributeMaxDynamicSharedMemorySize, GSMEM_BYTES);
    cudaFuncSetAttribute(gemm_mma<1>,
                         cudaFuncAttributeMaxDynamicSharedMemorySize, GSMEM_BYTES);
    cudaFuncSetAttribute(gemm_mma<2>,
                         cudaFuncAttributeMaxDynamicSharedMemorySize, GSMEM_BYTES);

    // ---- weight transposes ----
    dim3 tb(32, 8);
    transpose_kernel<<<dim3(CC / 32,  CC / 32),  tb>>>(Wq, WqT, CC,  CC);
    transpose_kernel<<<dim3(CC / 32,  CC / 32),  tb>>>(Wk, WkT, CC,  CC);
    transpose_kernel<<<dim3(CC / 32,  CC / 32),  tb>>>(Wv, WvT, CC,  CC);
    transpose_kernel<<<dim3(CC / 32,  CC / 32),  tb>>>(Wo, WoT, CC,  CC);
    transpose_kernel<<<dim3(WFF / 32, CC / 32),  tb>>>(W1, W1T, CC,  WFF);
    transpose_kernel<<<dim3(CC / 32,  WFF / 32), tb>>>(W2, W2T, WFF, CC);

    // LN1
    ln_kernel<<<MM, 256>>>(x, ln1w, ln1b, h);
    // QKV projections
    dim3 g1(CC / 128, MM / 128);
    gemm_mma<0><<<g1, 256, GSMEM_BYTES>>>(h, WqT, bq, nullptr, q, MM, CC, CC);
    gemm_mma<0><<<g1, 256, GSMEM_BYTES>>>(h, WkT, bk, nullptr, k, MM, CC, CC);
    gemm_mma<0><<<g1, 256, GSMEM_BYTES>>>(h, WvT, bv, nullptr, v, MM, CC, CC);
    // causal attention
    attn_kernel<<<dim3(TT / 64, HH, BB), 256, SMEM_ATTN>>>(q, k, v, y);
    // output projection + residual
    gemm_mma<2><<<g1, 256, GSMEM_BYTES>>>(y, WoT, bo, x, x2, MM, CC, CC);
    // LN2
    ln_kernel<<<MM, 256>>>(x2, ln2w, ln2b, h);
    // FF1 (relu)
    dim3 g2(WFF / 128, MM / 128);
    gemm_mma<1><<<g2, 256, GSMEM_BYTES>>>(h, W1T, b1, nullptr, ff, MM, WFF, CC);
    // FF2 + residual -> out
    gemm_mma<2><<<g1, 256, GSMEM_BYTES>>>(ff, W2T, b2, x2, out, MM, CC, WFF);
}

// round 4
// speedup vs baseline: 4.1961x; 1.8544x over previous
#include <cuda_runtime.h>
#include <cstdint>
#include <math.h>

#define BB  4
#define TT  2048
#define CC  1024
#define HH  16
#define DD  64
#define WFF 4096
#define MM  (BB*TT)   // 8192

// ---------------- scratch (device globals: allocation-free) ----------------
__device__ float g_h [(size_t)MM*CC];
__device__ float g_q [(size_t)MM*CC];
__device__ float g_k [(size_t)MM*CC];
__device__ float g_v [(size_t)MM*CC];
__device__ float g_y [(size_t)MM*CC];
__device__ float g_x2[(size_t)MM*CC];
__device__ float g_ff[(size_t)MM*WFF];
__device__ float g_wT[(size_t)4*CC*CC + (size_t)2*CC*WFF];

// ---------------- helpers ----------------------------------------------------
__device__ __forceinline__ uint32_t smem_u32(const void* p) {
    uint32_t a;
    asm("{ .reg .u64 t; cvta.to.shared.u64 t, %1; cvt.u32.u64 %0, t; }"
        : "=r"(a) : "l"(p));
    return a;
}
__device__ __forceinline__ void cp16(uint32_t s, const void* g) {
    asm volatile("cp.async.cg.shared.global [%0], [%1], 16;"
                 :: "r"(s), "l"(g) : "memory");
}
#define CP_COMMIT() asm volatile("cp.async.commit_group;" ::: "memory")
#define CP_WAIT0()  asm volatile("cp.async.wait_group 0;" ::: "memory")
#define CP_WAIT1()  asm volatile("cp.async.wait_group 1;" ::: "memory")

// round-to-nearest tf32 (kills RZ truncation bias of raw mma operands)
__device__ __forceinline__ float tf32r(float f) {
    uint32_t u;
    asm("cvt.rna.tf32.f32 %0, %1;" : "=r"(u) : "f"(f));
    return __uint_as_float(u);
}

__device__ __forceinline__ void mma_tf32(float* c, const uint32_t* a,
                                         const uint32_t* b) {
    asm volatile(
        "mma.sync.aligned.m16n8k8.row.col.f32.tf32.tf32.f32 "
        "{%0,%1,%2,%3}, {%4,%5,%6,%7}, {%8,%9}, {%0,%1,%2,%3};"
        : "+f"(c[0]), "+f"(c[1]), "+f"(c[2]), "+f"(c[3])
        : "r"(a[0]), "r"(a[1]), "r"(a[2]), "r"(a[3]),
          "r"(b[0]), "r"(b[1]));
}

// ---------------- weight transpose: dst[n,r] = round_tf32(src[r,n]) ---------
__global__ void __launch_bounds__(256) transpose_kernel(
    const float* __restrict__ src, float* __restrict__ dst, int R, int Ncols) {
    __shared__ float t[32][33];
    int bx = blockIdx.x * 32, by = blockIdx.y * 32;
    int tx = threadIdx.x, ty = threadIdx.y;
#pragma unroll
    for (int i = 0; i < 32; i += 8)
        t[ty + i][tx] = src[(size_t)(by + ty + i) * Ncols + bx + tx];
    __syncthreads();
#pragma unroll
    for (int i = 0; i < 32; i += 8)
        dst[(size_t)(bx + ty + i) * R + by + tx] = tf32r(t[tx][ty + i]);
}

// ---------------- LayerNorm (output rounded to tf32: GEMM-A operand) --------
__global__ void __launch_bounds__(256) ln_kernel(
    const float* __restrict__ X, const float* __restrict__ gw,
    const float* __restrict__ gb, float* __restrict__ O) {
    __shared__ float red[16];
    int row = blockIdx.x;
    int t = threadIdx.x;
    const float* xr = X + (size_t)row * CC;
    float4 v = *(const float4*)(xr + t * 4);
    float s  = v.x + v.y + v.z + v.w;
    float ss = v.x*v.x + v.y*v.y + v.z*v.z + v.w*v.w;
#pragma unroll
    for (int o = 16; o; o >>= 1) {
        s  += __shfl_down_sync(0xffffffffu, s,  o);
        ss += __shfl_down_sync(0xffffffffu, ss, o);
    }
    if ((t & 31) == 0) { red[t >> 5] = s; red[8 + (t >> 5)] = ss; }
    __syncthreads();
    if (t == 0) {
        float a = 0.f, c = 0.f;
#pragma unroll
        for (int i = 0; i < 8; i++) { a += red[i]; c += red[8 + i]; }
        float mean = a * (1.f / CC);
        float var  = c * (1.f / CC) - mean * mean;
        red[0] = mean;
        red[1] = rsqrtf(var + 1e-5f);
    }
    __syncthreads();
    float mean = red[0], rstd = red[1];
    float4 w4 = *(const float4*)(gw + t * 4);
    float4 b4 = *(const float4*)(gb + t * 4);
    float4 r;
    r.x = tf32r((v.x - mean) * rstd * w4.x + b4.x);
    r.y = tf32r((v.y - mean) * rstd * w4.y + b4.y);
    r.z = tf32r((v.z - mean) * rstd * w4.z + b4.z);
    r.w = tf32r((v.w - mean) * rstd * w4.w + b4.w);
    *(float4*)(O + (size_t)row * CC + t * 4) = r;
}

// ---------------- tf32 mma.sync GEMM: tile 128x128, BK=32 -------------------
// A: [M,K] row-major (values already tf32-rounded).  Bt: [N,K] row-major.
// EPI: 0 = bias (round out), 1 = bias+relu (round out), 2 = bias+residual (fp32)
#define GSMEM_BYTES 65536

template <int EPI>
__global__ void __launch_bounds__(256, 2) gemm_mma(
    const float* __restrict__ A, const float* __restrict__ Bt,
    const float* __restrict__ bias, const float* __restrict__ res,
    float* __restrict__ Cout, int M, int N, int K) {
    extern __shared__ float sm[];
    int tid = threadIdx.x;
    int wid = tid >> 5, lane = tid & 31;
    int gid = lane >> 2, tig = lane & 3;
    int wm = wid >> 1, wn = wid & 1;
    int bm = blockIdx.y << 7, bn = blockIdx.x << 7;

    const float* Ag = A  + (size_t)bm * K;
    const float* Bg = Bt + (size_t)bn * K;
    uint32_t smb = smem_u32(sm);

    auto load_chunk = [&](int c, int b) {
        const float* Ac = Ag + c * 32;
        const float* Bc = Bg + c * 32;
        uint32_t ab = smb + b * 32768;
        uint32_t bb = ab + 16384;
#pragma unroll
        for (int i = 0; i < 4; i++) {
            int idx = tid + (i << 8);
            int row = idx >> 3, c4 = idx & 7;
            uint32_t off = (uint32_t)(row * 128 + ((c4 * 16) ^ ((row & 7) * 16)));
            cp16(ab + off, Ac + (size_t)row * K + c4 * 4);
            cp16(bb + off, Bc + (size_t)row * K + c4 * 4);
        }
    };

    float acc[2][8][4];
#pragma unroll
    for (int mt = 0; mt < 2; mt++)
#pragma unroll
        for (int nt = 0; nt < 8; nt++)
#pragma unroll
            for (int r = 0; r < 4; r++) acc[mt][nt][r] = 0.f;

    int nc = K >> 5;
    load_chunk(0, 0);
    CP_COMMIT();

    for (int c = 0; c < nc; c++) {
        int b = c & 1;
        if (c + 1 < nc) {
            load_chunk(c + 1, b ^ 1);
            CP_COMMIT();
            CP_WAIT1();
        } else {
            CP_WAIT0();
        }
        __syncthreads();

        const float* sAb = sm + b * 8192;
        const float* sBb = sAb + 4096;
#pragma unroll
        for (int ks = 0; ks < 4; ks++) {
            int k0 = ks * 8 + tig;
            uint32_t aF[2][4], bF[8][2];
#pragma unroll
            for (int mt = 0; mt < 2; mt++) {
                int r0 = wm * 32 + mt * 16 + gid;
                const float* pa = sAb + r0 * 32;
                int sw = (r0 & 7) * 4;
                aF[mt][0] = __float_as_uint(pa[k0 ^ sw]);
                aF[mt][1] = __float_as_uint(pa[256 + (k0 ^ sw)]);
                aF[mt][2] = __float_as_uint(pa[(k0 + 4) ^ sw]);
                aF[mt][3] = __float_as_uint(pa[256 + ((k0 + 4) ^ sw)]);
            }
#pragma unroll
            for (int nt = 0; nt < 8; nt++) {
                int n0 = wn * 64 + nt * 8 + gid;
                const float* pb = sBb + n0 * 32;
                int sw = (n0 & 7) * 4;
                bF[nt][0] = __float_as_uint(pb[k0 ^ sw]);
                bF[nt][1] = __float_as_uint(pb[(k0 + 4) ^ sw]);
            }
#pragma unroll
            for (int mt = 0; mt < 2; mt++)
#pragma unroll
                for (int nt = 0; nt < 8; nt++)
                    mma_tf32(acc[mt][nt], aF[mt], bF[nt]);
        }
        __syncthreads();
    }

#pragma unroll
    for (int mt = 0; mt < 2; mt++) {
        int r0 = bm + wm * 32 + mt * 16 + gid;
#pragma unroll
        for (int half = 0; half < 2; half++) {
            int row = r0 + half * 8;
#pragma unroll
            for (int nt = 0; nt < 8; nt++) {
                int col = bn + wn * 64 + nt * 8 + tig * 2;
                float2 bv = *(const float2*)(bias + col);
                float2 o;
                o.x = acc[mt][nt][half * 2 + 0] + bv.x;
                o.y = acc[mt][nt][half * 2 + 1] + bv.y;
                if (EPI == 1) {
                    o.x = fmaxf(o.x, 0.f);
                    o.y = fmaxf(o.y, 0.f);
                }
                if (EPI == 2) {
                    float2 rr = *(const float2*)(res + (size_t)row * N + col);
                    o.x += rr.x; o.y += rr.y;
                } else {
                    // output feeds another tf32 GEMM / attention as A operand
                    o.x = tf32r(o.x); o.y = tf32r(o.y);
                }
                *(float2*)(Cout + (size_t)row * N + col) = o;
            }
        }
    }
}

// ---------------- tensor-core flash attention: BQ=128, BK=64, D=64 ----------
// SMEM: sK 64x64 (K-major swz), sV 64x64 (V^T, rotated swz), sPQ 128x64 (Q then P)
#define ASMEM_BYTES ((4096 + 4096 + 8192) * 4)   // 64 KB

__global__ void __launch_bounds__(256) attn_tc(
    const float* __restrict__ Q, const float* __restrict__ K,
    const float* __restrict__ V, float* __restrict__ Y) {
    extern __shared__ float sm[];
    float* sK  = sm;            // 4096 floats
    float* sV  = sK + 4096;     // 4096 floats (transposed V)
    float* sPQ = sV + 4096;     // 8192 floats (Q tile, then P per-warp)

    int qt = blockIdx.x, hh = blockIdx.y, b = blockIdx.z;
    int tid = threadIdx.x, wid = tid >> 5, lane = tid & 31;
    int gid = lane >> 2, tig = lane & 3;
    const size_t base = (size_t)b * TT * CC + hh * DD;
    int q0 = qt * 128;

    // ---- Q tile -> sPQ (plain swizzle), scaled by 1/8 (power of 2: exact) --
#pragma unroll
    for (int i = 0; i < 8; i++) {
        int idx = tid + i * 256;
        int row = idx >> 4, c4 = idx & 15;
        float4 v4 = *(const float4*)(Q + base + (size_t)(q0 + row) * CC + c4 * 4);
        float* p = sPQ + row * 64 + ((c4 ^ (row & 7)) << 2);
        p[0] = v4.x * 0.125f; p[1] = v4.y * 0.125f;
        p[2] = v4.z * 0.125f; p[3] = v4.w * 0.125f;
    }
    __syncthreads();

    // ---- Q fragments to registers (rows wid*16+gid, +8) --------------------
    uint32_t qf[8][4];
    {
        const float* p0 = sPQ + (wid * 16 + gid) * 64;
        const float* p1 = p0 + 8 * 64;
#pragma unroll
        for (int ks = 0; ks < 8; ks++) {
            int k0 = ks * 8 + tig;
            int a0 = (((k0 >> 2) ^ gid) << 2) + (k0 & 3);
            int a2 = ((((k0 + 4) >> 2) ^ gid) << 2) + (k0 & 3);
            qf[ks][0] = __float_as_uint(p0[a0]);
            qf[ks][1] = __float_as_uint(p1[a0]);
            qf[ks][2] = __float_as_uint(p0[a2]);
            qf[ks][3] = __float_as_uint(p1[a2]);
        }
    }

    // ---- K/V register prefetch + SMEM store helpers -------------------------
    float4 kreg[4], vreg[4];
    auto ldKV = [&](int t) {
        const float* Kg = K + base + (size_t)(t * 64) * CC;
        const float* Vg = V + base + (size_t)(t * 64) * CC;
#pragma unroll
        for (int i = 0; i < 4; i++) {
            int idx = tid + i * 256;
            int row = idx >> 4, c4 = idx & 15;
            kreg[i] = *(const float4*)(Kg + (size_t)row * CC + c4 * 4);
            vreg[i] = *(const float4*)(Vg + (size_t)row * CC + c4 * 4);
        }
    };
    auto stKV = [&]() {
#pragma unroll
        for (int i = 0; i < 4; i++) {
            int idx = tid + i * 256;
            int row = idx >> 4, c4 = idx & 15;
            *(float4*)(sK + row * 64 + ((c4 ^ (row & 7)) << 2)) = kreg[i];
            // V transposed: element (d = c4*4+j, key = row), rotated swizzle
            float vv[4] = {vreg[i].x, vreg[i].y, vreg[i].z, vreg[i].w};
#pragma unroll
            for (int j = 0; j < 4; j++) {
                int d = c4 * 4 + j;
                sV[d * 64 + ((((row >> 2) ^ (d & 7)) << 2)) + ((row + c4) & 3)] = vv[j];
            }
        }
    };

    float m_i[2] = {-1e30f, -1e30f}, l_i[2] = {0.f, 0.f};
    float oacc[8][4];
#pragma unroll
    for (int nt = 0; nt < 8; nt++)
#pragma unroll
        for (int r = 0; r < 4; r++) oacc[nt][r] = 0.f;

    int ntiles = 2 * qt + 2;
    ldKV(0);
    stKV();
    if (1 < ntiles) ldKV(1);
    __syncthreads();

    const int rbase = q0 + wid * 16 + gid;
    float* Pr0 = sPQ + (wid * 16 + gid) * 64;
    float* Pr1 = Pr0 + 8 * 64;

    for (int t = 0; t < ntiles; t++) {
        int k0t = t * 64;
        bool active = (k0t <= q0 + wid * 16 + 15);
        if (active) {
            // ---- S = (Q/8) @ K^T ----
            float sfr[8][4];
#pragma unroll
            for (int nt = 0; nt < 8; nt++)
#pragma unroll
                for (int r = 0; r < 4; r++) sfr[nt][r] = 0.f;
#pragma unroll
            for (int ks = 0; ks < 8; ks++) {
                int k0 = ks * 8 + tig;
                uint32_t bf[8][2];
#pragma unroll
                for (int nt = 0; nt < 8; nt++) {
                    const float* pb = sK + (nt * 8 + gid) * 64;
                    bf[nt][0] = __float_as_uint(pb[(((k0 >> 2) ^ gid) << 2) + (k0 & 3)]);
                    bf[nt][1] = __float_as_uint(pb[((((k0 + 4) >> 2) ^ gid) << 2) + (k0 & 3)]);
                }
#pragma unroll
                for (int nt = 0; nt < 8; nt++)
                    mma_tf32(sfr[nt], qf[ks], bf[nt]);
            }
            // ---- causal mask (only tiles near the diagonal) ----
            if (k0t + 63 > rbase) {
#pragma unroll
                for (int nt = 0; nt < 8; nt++) {
                    int cb = k0t + nt * 8 + tig * 2;
                    if (cb     > rbase)     sfr[nt][0] = -1e30f;
                    if (cb + 1 > rbase)     sfr[nt][1] = -1e30f;
                    if (cb     > rbase + 8) sfr[nt][2] = -1e30f;
                    if (cb + 1 > rbase + 8) sfr[nt][3] = -1e30f;
                }
            }
            // ---- online softmax per row-half ----
#pragma unroll
            for (int h = 0; h < 2; h++) {
                float rm = -1e30f;
#pragma unroll
                for (int nt = 0; nt < 8; nt++) {
                    rm = fmaxf(rm, fmaxf(sfr[nt][2 * h], sfr[nt][2 * h + 1]));
                }
                rm = fmaxf(rm, __shfl_xor_sync(0xffffffffu, rm, 1));
                rm = fmaxf(rm, __shfl_xor_sync(0xffffffffu, rm, 2));
                float mn = fmaxf(m_i[h], rm);
                float alpha = __expf(m_i[h] - mn);
                m_i[h] = mn;
                float rs = 0.f;
                float* Pr = h ? Pr1 : Pr0;
#pragma unroll
                for (int nt = 0; nt < 8; nt++) {
                    float p0 = __expf(sfr[nt][2 * h]     - mn);
                    float p1 = __expf(sfr[nt][2 * h + 1] - mn);
                    rs += p0 + p1;
                    int col = nt * 8 + tig * 2;
                    int ch = ((col >> 2) ^ gid) << 2;
                    *(float2*)(Pr + ch + (col & 3)) =
                        make_float2(tf32r(p0), tf32r(p1));
                    oacc[nt][2 * h]     *= alpha;
                    oacc[nt][2 * h + 1] *= alpha;
                }
                rs += __shfl_xor_sync(0xffffffffu, rs, 1);
                rs += __shfl_xor_sync(0xffffffffu, rs, 2);
                l_i[h] = l_i[h] * alpha + rs;
            }
            __syncwarp();
            // ---- O += P @ V ----
#pragma unroll
            for (int ks = 0; ks < 8; ks++) {
                int kk = ks * 8 + tig;
                int a0 = (((kk >> 2) ^ gid) << 2) + (kk & 3);
                int a2 = ((((kk + 4) >> 2) ^ gid) << 2) + (kk & 3);
                uint32_t af[4];
                af[0] = __float_as_uint(Pr0[a0]);
                af[1] = __float_as_uint(Pr1[a0]);
                af[2] = __float_as_uint(Pr0[a2]);
                af[3] = __float_as_uint(Pr1[a2]);
                uint32_t bf[8][2];
#pragma unroll
                for (int nt = 0; nt < 8; nt++) {
                    int d = nt * 8 + gid;
                    const float* pv = sV + d * 64;
                    int dc = d >> 2;
                    int c0 = (((kk >> 2) ^ (d & 7)) << 2) + ((kk + dc) & 3);
                    int c1 = ((((kk + 4) >> 2) ^ (d & 7)) << 2) + ((kk + dc) & 3);
                    bf[nt][0] = __float_as_uint(pv[c0]);
                    bf[nt][1] = __float_as_uint(pv[c1]);
                }
#pragma unroll
                for (int nt = 0; nt < 8; nt++)
                    mma_tf32(oacc[nt], af, bf[nt]);
            }
        }
        // ---- pipeline advance ----
        __syncthreads();
        if (t + 1 < ntiles) {
            stKV();
            if (t + 2 < ntiles) ldKV(t + 2);
            __syncthreads();
        }
    }

    // ---- output (rounded to tf32: feeds Wo GEMM as A operand) --------------
#pragma unroll
    for (int h = 0; h < 2; h++) {
        float inv = 1.f / l_i[h];
        float* yr = (float*)(Y + base + (size_t)(rbase + h * 8) * CC);
#pragma unroll
        for (int nt = 0; nt < 8; nt++) {
            int col = nt * 8 + tig * 2;
            *(float2*)(yr + col) = make_float2(
                tf32r(oacc[nt][2 * h] * inv), tf32r(oacc[nt][2 * h + 1] * inv));
        }
    }
}

// ---------------- launch ---------------------------------------------------
extern "C" void kernel_launch(void* const* d_in, const int* in_sizes, int n_in,
                              void* d_out, int out_size) {
    const float* x    = (const float*)d_in[0];
    const float* ln1w = (const float*)d_in[1];
    const float* ln1b = (const float*)d_in[2];
    const float* Wq   = (const float*)d_in[3];
    const float* bq   = (const float*)d_in[4];
    const float* Wk   = (const float*)d_in[5];
    const float* bk   = (const float*)d_in[6];
    const float* Wv   = (const float*)d_in[7];
    const float* bv   = (const float*)d_in[8];
    const float* Wo   = (const float*)d_in[9];
    const float* bo   = (const float*)d_in[10];
    const float* ln2w = (const float*)d_in[11];
    const float* ln2b = (const float*)d_in[12];
    const float* W1   = (const float*)d_in[13];
    const float* b1   = (const float*)d_in[14];
    const float* W2   = (const float*)d_in[15];
    const float* b2   = (const float*)d_in[16];
    float* out = (float*)d_out;

    float *h, *q, *k, *v, *y, *x2, *ff, *wT;
    cudaGetSymbolAddress((void**)&h,  g_h);
    cudaGetSymbolAddress((void**)&q,  g_q);
    cudaGetSymbolAddress((void**)&k,  g_k);
    cudaGetSymbolAddress((void**)&v,  g_v);
    cudaGetSymbolAddress((void**)&y,  g_y);
    cudaGetSymbolAddress((void**)&x2, g_x2);
    cudaGetSymbolAddress((void**)&ff, g_ff);
    cudaGetSymbolAddress((void**)&wT, g_wT);

    float* WqT = wT;
    float* WkT = WqT + (size_t)CC * CC;
    float* WvT = WkT + (size_t)CC * CC;
    float* WoT = WvT + (size_t)CC * CC;
    float* W1T = WoT + (size_t)CC * CC;          // [WFF, CC]
    float* W2T = W1T + (size_t)CC * WFF;         // [CC, WFF]

    cudaFuncSetAttribute(attn_tc,
                         cudaFuncAttributeMaxDynamicSharedMemorySize, ASMEM_BYTES);
    cudaFuncSetAttribute(gemm_mma<0>,
                         cudaFuncAttributeMaxDynamicSharedMemorySize, GSMEM_BYTES);
    cudaFuncSetAttribute(gemm_mma<1>,
                         cudaFuncAttributeMaxDynamicSharedMemorySize, GSMEM_BYTES);
    cudaFuncSetAttribute(gemm_mma<2>,
                         cudaFuncAttributeMaxDynamicSharedMemorySize, GSMEM_BYTES);

    // ---- weight transposes (+ tf32 rounding) ----
    dim3 tb(32, 8);
    transpose_kernel<<<dim3(CC / 32,  CC / 32),  tb>>>(Wq, WqT, CC,  CC);
    transpose_kernel<<<dim3(CC / 32,  CC / 32),  tb>>>(Wk, WkT, CC,  CC);
    transpose_kernel<<<dim3(CC / 32,  CC / 32),  tb>>>(Wv, WvT, CC,  CC);
    transpose_kernel<<<dim3(CC / 32,  CC / 32),  tb>>>(Wo, WoT, CC,  CC);
    transpose_kernel<<<dim3(WFF / 32, CC / 32),  tb>>>(W1, W1T, CC,  WFF);
    transpose_kernel<<<dim3(CC / 32,  WFF / 32), tb>>>(W2, W2T, WFF, CC);

    // LN1
    ln_kernel<<<MM, 256>>>(x, ln1w, ln1b, h);
    // QKV projections
    dim3 g1(CC / 128, MM / 128);
    gemm_mma<0><<<g1, 256, GSMEM_BYTES>>>(h, WqT, bq, nullptr, q, MM, CC, CC);
    gemm_mma<0><<<g1, 256, GSMEM_BYTES>>>(h, WkT, bk, nullptr, k, MM, CC, CC);
    gemm_mma<0><<<g1, 256, GSMEM_BYTES>>>(h, WvT, bv, nullptr, v, MM, CC, CC);
    // causal attention (tensor cores)
    attn_tc<<<dim3(TT / 128, HH, BB), 256, ASMEM_BYTES>>>(q, k, v, y);
    // output projection + residual
    gemm_mma<2><<<g1, 256, GSMEM_BYTES>>>(y, WoT, bo, x, x2, MM, CC, CC);
    // LN2
    ln_kernel<<<MM, 256>>>(x2, ln2w, ln2b, h);
    // FF1 (relu)
    dim3 g2(WFF / 128, MM / 128);
    gemm_mma<1><<<g2, 256, GSMEM_BYTES>>>(h, W1T, b1, nullptr, ff, MM, WFF, CC);
    // FF2 + residual -> out
    gemm_mma<2><<<g1, 256, GSMEM_BYTES>>>(ff, W2T, b2, x2, out, MM, CC, WFF);
}

// round 5
// speedup vs baseline: 8.8707x; 2.1140x over previous
#include <cuda_runtime.h>
#include <cuda_fp16.h>
#include <cstdint>
#include <math.h>

#define BB  4
#define TT  2048
#define CC  1024
#define HH  16
#define DD  64
#define WFF 4096
#define MM  (BB*TT)   // 8192
#define C3  (3*CC)    // 3072

// ---------------- scratch (device globals: allocation-free) ----------------
__device__ __half g_h  [(size_t)MM*CC];
__device__ __half g_qkv[(size_t)MM*C3];
__device__ __half g_y  [(size_t)MM*CC];
__device__ float  g_x2 [(size_t)MM*CC];
__device__ __half g_ff [(size_t)MM*WFF];
__device__ __half g_wT [(size_t)4*CC*CC + (size_t)2*CC*WFF];
__device__ float  g_bqkv[C3];

// ---------------- helpers ----------------------------------------------------
__device__ __forceinline__ uint32_t smem_u32(const void* p) {
    uint32_t a;
    asm("{ .reg .u64 t; cvta.to.shared.u64 t, %1; cvt.u32.u64 %0, t; }"
        : "=r"(a) : "l"(p));
    return a;
}
__device__ __forceinline__ void cp16(uint32_t s, const void* g) {
    asm volatile("cp.async.cg.shared.global [%0], [%1], 16;"
                 :: "r"(s), "l"(g) : "memory");
}
#define CP_COMMIT() asm volatile("cp.async.commit_group;" ::: "memory")
#define CP_WAIT0()  asm volatile("cp.async.wait_group 0;" ::: "memory")
#define CP_WAIT1()  asm volatile("cp.async.wait_group 1;" ::: "memory")

__device__ __forceinline__ void ldsm4(uint32_t* r, uint32_t a) {
    asm volatile("ldmatrix.sync.aligned.m8n8.x4.shared.b16 {%0,%1,%2,%3}, [%4];"
                 : "=r"(r[0]), "=r"(r[1]), "=r"(r[2]), "=r"(r[3]) : "r"(a));
}
__device__ __forceinline__ void ldsm4t(uint32_t* r, uint32_t a) {
    asm volatile("ldmatrix.sync.aligned.m8n8.x4.trans.shared.b16 {%0,%1,%2,%3}, [%4];"
                 : "=r"(r[0]), "=r"(r[1]), "=r"(r[2]), "=r"(r[3]) : "r"(a));
}
__device__ __forceinline__ void mma_f16(float* c, const uint32_t* a,
                                        const uint32_t* b) {
    asm volatile(
        "mma.sync.aligned.m16n8k16.row.col.f32.f16.f16.f32 "
        "{%0,%1,%2,%3}, {%4,%5,%6,%7}, {%8,%9}, {%0,%1,%2,%3};"
        : "+f"(c[0]), "+f"(c[1]), "+f"(c[2]), "+f"(c[3])
        : "r"(a[0]), "r"(a[1]), "r"(a[2]), "r"(a[3]),
          "r"(b[0]), "r"(b[1]));
}
// swizzled byte offset: row r (64-half rows = 8 x 16B units), unit u
__device__ __forceinline__ uint32_t swz(int r, int u) {
    return (uint32_t)(((r << 3) + (u ^ (r & 7))) << 4);
}

// ---------------- weight transpose: dst[n,r] = half(src[r,n]) ----------------
__global__ void __launch_bounds__(256) transpose_kernel(
    const float* __restrict__ src, __half* __restrict__ dst, int R, int Ncols) {
    __shared__ float t[32][33];
    int bx = blockIdx.x * 32, by = blockIdx.y * 32;
    int tx = threadIdx.x, ty = threadIdx.y;
#pragma unroll
    for (int i = 0; i < 32; i += 8)
        t[ty + i][tx] = src[(size_t)(by + ty + i) * Ncols + bx + tx];
    __syncthreads();
#pragma unroll
    for (int i = 0; i < 32; i += 8)
        dst[(size_t)(bx + ty + i) * R + by + tx] = __float2half(t[tx][ty + i]);
}

// ---------------- concat QKV bias -------------------------------------------
__global__ void concat_bias(const float* __restrict__ a,
                            const float* __restrict__ b,
                            const float* __restrict__ c,
                            float* __restrict__ o) {
    int t = blockIdx.x * 256 + threadIdx.x;
    if (t < CC)            o[t] = a[t];
    else if (t < 2 * CC)   o[t] = b[t - CC];
    else if (t < 3 * CC)   o[t] = c[t - 2 * CC];
}

// ---------------- LayerNorm (fp32 in, fp16 out) ------------------------------
__global__ void __launch_bounds__(256) ln_kernel(
    const float* __restrict__ X, const float* __restrict__ gw,
    const float* __restrict__ gb, __half* __restrict__ O) {
    __shared__ float red[16];
    int row = blockIdx.x;
    int t = threadIdx.x;
    const float* xr = X + (size_t)row * CC;
    float4 v = *(const float4*)(xr + t * 4);
    float s  = v.x + v.y + v.z + v.w;
    float ss = v.x*v.x + v.y*v.y + v.z*v.z + v.w*v.w;
#pragma unroll
    for (int o = 16; o; o >>= 1) {
        s  += __shfl_down_sync(0xffffffffu, s,  o);
        ss += __shfl_down_sync(0xffffffffu, ss, o);
    }
    if ((t & 31) == 0) { red[t >> 5] = s; red[8 + (t >> 5)] = ss; }
    __syncthreads();
    if (t == 0) {
        float a = 0.f, c = 0.f;
#pragma unroll
        for (int i = 0; i < 8; i++) { a += red[i]; c += red[8 + i]; }
        float mean = a * (1.f / CC);
        float var  = c * (1.f / CC) - mean * mean;
        red[0] = mean;
        red[1] = rsqrtf(var + 1e-5f);
    }
    __syncthreads();
    float mean = red[0], rstd = red[1];
    float4 w4 = *(const float4*)(gw + t * 4);
    float4 b4 = *(const float4*)(gb + t * 4);
    __half2* op = (__half2*)(O + (size_t)row * CC);
    op[t * 2 + 0] = __floats2half2_rn((v.x - mean) * rstd * w4.x + b4.x,
                                      (v.y - mean) * rstd * w4.y + b4.y);
    op[t * 2 + 1] = __floats2half2_rn((v.z - mean) * rstd * w4.z + b4.z,
                                      (v.w - mean) * rstd * w4.w + b4.w);
}

// ---------------- fp16 mma GEMM: tile 128x128, BK=64 ------------------------
// A: [M,K] fp16 row-major.  Bt: [N,K] fp16 row-major.
// EPI: 0 = bias -> fp16 out, 1 = bias+relu -> fp16 out, 2 = bias+residual -> fp32 out
#define GSMEM_BYTES 65536   // 2 bufs x (A 16KB + B 16KB)

template <int EPI>
__global__ void __launch_bounds__(256, 2) gemm_h(
    const __half* __restrict__ A, const __half* __restrict__ Bt,
    const float* __restrict__ bias, const float* __restrict__ res,
    void* __restrict__ Cout_, int M, int N, int K) {
    extern __shared__ char smc[];
    int tid = threadIdx.x, wid = tid >> 5, lane = tid & 31;
    int gid = lane >> 2, tig = lane & 3;
    int wm = wid >> 1, wn = wid & 1;
    int bm = blockIdx.y << 7, bn = blockIdx.x << 7;

    const __half* Ag = A  + (size_t)bm * K;
    const __half* Bg = Bt + (size_t)bn * K;
    uint32_t smb = smem_u32(smc);

    auto load_chunk = [&](int c, int b) {
        const __half* Ac = Ag + c * 64;
        const __half* Bc = Bg + c * 64;
        uint32_t ab = smb + b * 32768;
        uint32_t bb = ab + 16384;
#pragma unroll
        for (int i = 0; i < 4; i++) {
            int idx = tid + (i << 8);
            int row = idx >> 3, u = idx & 7;
            uint32_t off = swz(row, u);
            cp16(ab + off, Ac + (size_t)row * K + (u << 3));
            cp16(bb + off, Bc + (size_t)row * K + (u << 3));
        }
    };

    float acc[2][8][4];
#pragma unroll
    for (int mt = 0; mt < 2; mt++)
#pragma unroll
        for (int nt = 0; nt < 8; nt++)
#pragma unroll
            for (int r = 0; r < 4; r++) acc[mt][nt][r] = 0.f;

    const int l15 = lane & 15, l7 = lane & 7;
    const int aU = lane >> 4;              // A/Q unit add
    const int bR = (lane >> 4) << 3;       // B row add
    const int bU = (lane >> 3) & 1;        // B unit add

    int nc = K >> 6;
    load_chunk(0, 0);
    CP_COMMIT();

    for (int c = 0; c < nc; c++) {
        int b = c & 1;
        if (c + 1 < nc) {
            load_chunk(c + 1, b ^ 1);
            CP_COMMIT();
            CP_WAIT1();
        } else {
            CP_WAIT0();
        }
        __syncthreads();

        uint32_t sA = smb + b * 32768;
        uint32_t sB = sA + 16384;
#pragma unroll
        for (int ks = 0; ks < 4; ks++) {
            uint32_t aF[2][4], bF[8][2];
#pragma unroll
            for (int mt = 0; mt < 2; mt++) {
                int r = wm * 32 + mt * 16 + l15;
                ldsm4(aF[mt], sA + swz(r, 2 * ks + aU));
            }
#pragma unroll
            for (int ntp = 0; ntp < 4; ntp++) {
                int r = wn * 64 + ntp * 16 + l7 + bR;
                uint32_t t4[4];
                ldsm4(t4, sB + swz(r, 2 * ks + bU));
                bF[2 * ntp][0] = t4[0]; bF[2 * ntp][1] = t4[1];
                bF[2 * ntp + 1][0] = t4[2]; bF[2 * ntp + 1][1] = t4[3];
            }
#pragma unroll
            for (int mt = 0; mt < 2; mt++)
#pragma unroll
                for (int nt = 0; nt < 8; nt++)
                    mma_f16(acc[mt][nt], aF[mt], bF[nt]);
        }
        __syncthreads();
    }

    // ---- epilogue ----
#pragma unroll
    for (int mt = 0; mt < 2; mt++) {
        int r0 = bm + wm * 32 + mt * 16 + gid;
#pragma unroll
        for (int half = 0; half < 2; half++) {
            int row = r0 + half * 8;
#pragma unroll
            for (int nt = 0; nt < 8; nt++) {
                int col = bn + wn * 64 + nt * 8 + tig * 2;
                float2 bv = *(const float2*)(bias + col);
                float ox = acc[mt][nt][half * 2 + 0] + bv.x;
                float oy = acc[mt][nt][half * 2 + 1] + bv.y;
                if (EPI == 1) { ox = fmaxf(ox, 0.f); oy = fmaxf(oy, 0.f); }
                if (EPI == 2) {
                    float2 rr = *(const float2*)(res + (size_t)row * N + col);
                    float* Co = (float*)Cout_;
                    *(float2*)(Co + (size_t)row * N + col) =
                        make_float2(ox + rr.x, oy + rr.y);
                } else {
                    __half* Co = (__half*)Cout_;
                    *(__half2*)(Co + (size_t)row * N + col) =
                        __floats2half2_rn(ox, oy);
                }
            }
        }
    }
}

// ---------------- fp16 flash attention: BQ=128, BK=64, D=64 -----------------
// smem: sQ 16KB | sK 2x8KB | sV 2x8KB | sP 16KB  = 64KB
#define AS_Q 0
#define AS_K 16384
#define AS_V 32768
#define AS_P 49152
#define ASMEM_BYTES 65536

__global__ void __launch_bounds__(256) attn_h(
    const __half* __restrict__ QKV, __half* __restrict__ Y) {
    extern __shared__ char smc[];
    uint32_t smb = smem_u32(smc);
    int qt = blockIdx.x, hh = blockIdx.y, b = blockIdx.z;
    int tid = threadIdx.x, wid = tid >> 5, lane = tid & 31;
    int gid = lane >> 2, tig = lane & 3;
    int q0 = qt * 128;

    const __half* Qg = QKV + (size_t)b * TT * C3 + hh * DD;
    const __half* Kg = Qg + CC;
    const __half* Vg = Qg + 2 * CC;

    const int l15 = lane & 15, l7 = lane & 7;
    const int aU = lane >> 4;
    const int bR = (lane >> 4) << 3;
    const int bU = (lane >> 3) & 1;

    // ---- Q tile load (group 0) ----
#pragma unroll
    for (int i = 0; i < 4; i++) {
        int idx = tid + (i << 8);
        int row = idx >> 3, u = idx & 7;
        cp16(smb + AS_Q + swz(row, u), Qg + (size_t)(q0 + row) * C3 + (u << 3));
    }
    CP_COMMIT();

    auto loadKV = [&](int t, int bf) {
        const __half* Kt = Kg + (size_t)(t * 64) * C3;
        const __half* Vt = Vg + (size_t)(t * 64) * C3;
        uint32_t dk = smb + AS_K + bf * 8192;
        uint32_t dv = smb + AS_V + bf * 8192;
#pragma unroll
        for (int i = 0; i < 2; i++) {
            int idx = tid + (i << 8);
            int row = idx >> 3, u = idx & 7;
            uint32_t off = swz(row, u);
            cp16(dk + off, Kt + (size_t)row * C3 + (u << 3));
            cp16(dv + off, Vt + (size_t)row * C3 + (u << 3));
        }
    };

    int ntiles = 2 * qt + 2;
    loadKV(0, 0); CP_COMMIT();
    loadKV(1, 1); CP_COMMIT();
    CP_WAIT1();          // Q + KV0 complete (KV1 may pend)
    __syncthreads();

    // ---- Q fragments ----
    uint32_t qf[4][4];
#pragma unroll
    for (int ks = 0; ks < 4; ks++) {
        int r = wid * 16 + l15;
        ldsm4(qf[ks], smb + AS_Q + swz(r, 2 * ks + aU));
    }

    float m_i[2] = {-1e30f, -1e30f}, l_i[2] = {0.f, 0.f};
    float oacc[8][4];
#pragma unroll
    for (int nt = 0; nt < 8; nt++)
#pragma unroll
        for (int r = 0; r < 4; r++) oacc[nt][r] = 0.f;

    const int rbase = q0 + wid * 16 + gid;

    for (int t = 0; t < ntiles; t++) {
        int bf = t & 1;
        int k0t = t * 64;
        bool active = (k0t <= q0 + wid * 16 + 15);
        if (active) {
            uint32_t sK = smb + AS_K + bf * 8192;
            uint32_t sV = smb + AS_V + bf * 8192;
            // ---- S = Q @ K^T ----
            float sfr[8][4];
#pragma unroll
            for (int nt = 0; nt < 8; nt++)
#pragma unroll
                for (int r = 0; r < 4; r++) sfr[nt][r] = 0.f;
#pragma unroll
            for (int ks = 0; ks < 4; ks++) {
                uint32_t bF[8][2];
#pragma unroll
                for (int ntp = 0; ntp < 4; ntp++) {
                    int r = ntp * 16 + l7 + bR;
                    uint32_t t4[4];
                    ldsm4(t4, sK + swz(r, 2 * ks + bU));
                    bF[2 * ntp][0] = t4[0]; bF[2 * ntp][1] = t4[1];
                    bF[2 * ntp + 1][0] = t4[2]; bF[2 * ntp + 1][1] = t4[3];
                }
#pragma unroll
                for (int nt = 0; nt < 8; nt++)
                    mma_f16(sfr[nt], qf[ks], bF[nt]);
            }
            // ---- scale + causal mask ----
#pragma unroll
            for (int nt = 0; nt < 8; nt++)
#pragma unroll
                for (int r = 0; r < 4; r++) sfr[nt][r] *= 0.125f;
            if (k0t + 63 > rbase) {
#pragma unroll
                for (int nt = 0; nt < 8; nt++) {
                    int cb = k0t + nt * 8 + tig * 2;
                    if (cb     > rbase)     sfr[nt][0] = -1e30f;
                    if (cb + 1 > rbase)     sfr[nt][1] = -1e30f;
                    if (cb     > rbase + 8) sfr[nt][2] = -1e30f;
                    if (cb + 1 > rbase + 8) sfr[nt][3] = -1e30f;
                }
            }
            // ---- online softmax; write P (fp16) to per-warp smem ----
#pragma unroll
            for (int h = 0; h < 2; h++) {
                float rm = -1e30f;
#pragma unroll
                for (int nt = 0; nt < 8; nt++)
                    rm = fmaxf(rm, fmaxf(sfr[nt][2 * h], sfr[nt][2 * h + 1]));
                rm = fmaxf(rm, __shfl_xor_sync(0xffffffffu, rm, 1));
                rm = fmaxf(rm, __shfl_xor_sync(0xffffffffu, rm, 2));
                float mn = fmaxf(m_i[h], rm);
                float alpha = __expf(m_i[h] - mn);
                m_i[h] = mn;
                float rs = 0.f;
                int pr = wid * 16 + gid + h * 8;
#pragma unroll
                for (int nt = 0; nt < 8; nt++) {
                    float p0 = __expf(sfr[nt][2 * h]     - mn);
                    float p1 = __expf(sfr[nt][2 * h + 1] - mn);
                    rs += p0 + p1;
                    int col = nt * 8 + tig * 2;
                    *(__half2*)(smc + AS_P + swz(pr, col >> 3) + (col & 7) * 2) =
                        __floats2half2_rn(p0, p1);
                    oacc[nt][2 * h]     *= alpha;
                    oacc[nt][2 * h + 1] *= alpha;
                }
                rs += __shfl_xor_sync(0xffffffffu, rs, 1);
                rs += __shfl_xor_sync(0xffffffffu, rs, 2);
                l_i[h] = l_i[h] * alpha + rs;
            }
            __syncwarp();
            // ---- O += P @ V  (V via ldmatrix.trans, no transpose stores) ----
#pragma unroll
            for (int ks = 0; ks < 4; ks++) {
                uint32_t pf[4];
                {
                    int r = wid * 16 + l15;
                    ldsm4(pf, smb + AS_P + swz(r, 2 * ks + aU));
                }
#pragma unroll
                for (int ntp = 0; ntp < 4; ntp++) {
                    int kk = ks * 16 + l7 + ((lane >> 3) & 1) * 8;
                    uint32_t t4[4];
                    ldsm4t(t4, sV + swz(kk, 2 * ntp + aU));
                    mma_f16(oacc[2 * ntp],     pf, t4);
                    mma_f16(oacc[2 * ntp + 1], pf, t4 + 2);
                }
            }
        }
        __syncthreads();   // all warps done with buf bf
        if (t + 2 < ntiles) {
            loadKV(t + 2, bf);
            CP_COMMIT();
            CP_WAIT1();    // tile t+1 complete
            __syncthreads();
        } else if (t + 1 < ntiles) {
            CP_WAIT0();
            __syncthreads();
        }
    }

    // ---- output (fp16, feeds Wo GEMM) ----
    __half* Yg = Y + (size_t)b * TT * CC + hh * DD;
#pragma unroll
    for (int h = 0; h < 2; h++) {
        float inv = 1.f / l_i[h];
        __half* yr = Yg + (size_t)(rbase + h * 8) * CC;
#pragma unroll
        for (int nt = 0; nt < 8; nt++) {
            int col = nt * 8 + tig * 2;
            *(__half2*)(yr + col) = __floats2half2_rn(
                oacc[nt][2 * h] * inv, oacc[nt][2 * h + 1] * inv);
        }
    }
}

// ---------------- launch ---------------------------------------------------
extern "C" void kernel_launch(void* const* d_in, const int* in_sizes, int n_in,
                              void* d_out, int out_size) {
    const float* x    = (const float*)d_in[0];
    const float* ln1w = (const float*)d_in[1];
    const float* ln1b = (const float*)d_in[2];
    const float* Wq   = (const float*)d_in[3];
    const float* bq   = (const float*)d_in[4];
    const float* Wk   = (const float*)d_in[5];
    const float* bk   = (const float*)d_in[6];
    const float* Wv   = (const float*)d_in[7];
    const float* bv   = (const float*)d_in[8];
    const float* Wo   = (const float*)d_in[9];
    const float* bo   = (const float*)d_in[10];
    const float* ln2w = (const float*)d_in[11];
    const float* ln2b = (const float*)d_in[12];
    const float* W1   = (const float*)d_in[13];
    const float* b1   = (const float*)d_in[14];
    const float* W2   = (const float*)d_in[15];
    const float* b2   = (const float*)d_in[16];
    float* out = (float*)d_out;

    __half *h, *qkv, *y, *ff, *wT;
    float *x2, *bqkv;
    cudaGetSymbolAddress((void**)&h,    g_h);
    cudaGetSymbolAddress((void**)&qkv,  g_qkv);
    cudaGetSymbolAddress((void**)&y,    g_y);
    cudaGetSymbolAddress((void**)&x2,   g_x2);
    cudaGetSymbolAddress((void**)&ff,   g_ff);
    cudaGetSymbolAddress((void**)&wT,   g_wT);
    cudaGetSymbolAddress((void**)&bqkv, g_bqkv);

    __half* WqkvT = wT;                                  // [3C, C]
    __half* WoT   = WqkvT + (size_t)3 * CC * CC;         // [C, C]
    __half* W1T   = WoT + (size_t)CC * CC;               // [WFF, C]
    __half* W2T   = W1T + (size_t)CC * WFF;              // [C, WFF]

    cudaFuncSetAttribute(attn_h,
                         cudaFuncAttributeMaxDynamicSharedMemorySize, ASMEM_BYTES);
    cudaFuncSetAttribute(gemm_h<0>,
                         cudaFuncAttributeMaxDynamicSharedMemorySize, GSMEM_BYTES);
    cudaFuncSetAttribute(gemm_h<1>,
                         cudaFuncAttributeMaxDynamicSharedMemorySize, GSMEM_BYTES);
    cudaFuncSetAttribute(gemm_h<2>,
                         cudaFuncAttributeMaxDynamicSharedMemorySize, GSMEM_BYTES);

    // ---- weight transposes (fp32 -> fp16) + bias concat ----
    dim3 tb(32, 8);
    transpose_kernel<<<dim3(CC / 32,  CC / 32),  tb>>>(Wq, WqkvT,                        CC,  CC);
    transpose_kernel<<<dim3(CC / 32,  CC / 32),  tb>>>(Wk, WqkvT + (size_t)CC * CC,      CC,  CC);
    transpose_kernel<<<dim3(CC / 32,  CC / 32),  tb>>>(Wv, WqkvT + (size_t)2 * CC * CC,  CC,  CC);
    transpose_kernel<<<dim3(CC / 32,  CC / 32),  tb>>>(Wo, WoT, CC,  CC);
    transpose_kernel<<<dim3(WFF / 32, CC / 32),  tb>>>(W1, W1T, CC,  WFF);
    transpose_kernel<<<dim3(CC / 32,  WFF / 32), tb>>>(W2, W2T, WFF, CC);
    concat_bias<<<12, 256>>>(bq, bk, bv, bqkv);

    // LN1
    ln_kernel<<<MM, 256>>>(x, ln1w, ln1b, h);
    // fused QKV projection (N = 3072)
    gemm_h<0><<<dim3(C3 / 128, MM / 128), 256, GSMEM_BYTES>>>(
        h, WqkvT, bqkv, nullptr, qkv, MM, C3, CC);
    // causal attention
    attn_h<<<dim3(TT / 128, HH, BB), 256, ASMEM_BYTES>>>(qkv, y);
    // output projection + residual
    dim3 g1(CC / 128, MM / 128);
    gemm_h<2><<<g1, 256, GSMEM_BYTES>>>(y, WoT, bo, x, x2, MM, CC, CC);
    // LN2
    ln_kernel<<<MM, 256>>>(x2, ln2w, ln2b, h);
    // FF1 (relu)
    gemm_h<1><<<dim3(WFF / 128, MM / 128), 256, GSMEM_BYTES>>>(
        h, W1T, b1, nullptr, ff, MM, WFF, CC);
    // FF2 + residual -> out
    gemm_h<2><<<g1, 256, GSMEM_BYTES>>>(ff, W2T, b2, x2, out, MM, CC, WFF);
}

// round 6
// speedup vs baseline: 8.9737x; 1.0116x over previous
#include <cuda_runtime.h>
#include <cuda_fp16.h>
#include <cstdint>
#include <math.h>

#define BB  4
#define TT  2048
#define CC  1024
#define HH  16
#define DD  64
#define WFF 4096
#define MM  (BB*TT)   // 8192
#define C3  (3*CC)    // 3072

// ---------------- scratch (device globals: allocation-free) ----------------
__device__ __half g_h  [(size_t)MM*CC];
__device__ __half g_qkv[(size_t)MM*C3];
__device__ __half g_y  [(size_t)MM*CC];
__device__ float  g_x2 [(size_t)MM*CC];
__device__ __half g_ff [(size_t)MM*WFF];
__device__ __half g_wT [(size_t)4*CC*CC + (size_t)2*CC*WFF];
__device__ float  g_bqkv[C3];

// ---------------- helpers ----------------------------------------------------
__device__ __forceinline__ uint32_t smem_u32(const void* p) {
    uint32_t a;
    asm("{ .reg .u64 t; cvta.to.shared.u64 t, %1; cvt.u32.u64 %0, t; }"
        : "=r"(a) : "l"(p));
    return a;
}
__device__ __forceinline__ void cp16(uint32_t s, const void* g) {
    asm volatile("cp.async.cg.shared.global [%0], [%1], 16;"
                 :: "r"(s), "l"(g) : "memory");
}
#define CP_COMMIT() asm volatile("cp.async.commit_group;" ::: "memory")
#define CP_WAIT0()  asm volatile("cp.async.wait_group 0;" ::: "memory")
#define CP_WAIT1()  asm volatile("cp.async.wait_group 1;" ::: "memory")

__device__ __forceinline__ void ldsm4(uint32_t* r, uint32_t a) {
    asm volatile("ldmatrix.sync.aligned.m8n8.x4.shared.b16 {%0,%1,%2,%3}, [%4];"
                 : "=r"(r[0]), "=r"(r[1]), "=r"(r[2]), "=r"(r[3]) : "r"(a));
}
__device__ __forceinline__ void ldsm4t(uint32_t* r, uint32_t a) {
    asm volatile("ldmatrix.sync.aligned.m8n8.x4.trans.shared.b16 {%0,%1,%2,%3}, [%4];"
                 : "=r"(r[0]), "=r"(r[1]), "=r"(r[2]), "=r"(r[3]) : "r"(a));
}
__device__ __forceinline__ void mma_f16(float* c, const uint32_t* a,
                                        const uint32_t* b) {
    asm volatile(
        "mma.sync.aligned.m16n8k16.row.col.f32.f16.f16.f32 "
        "{%0,%1,%2,%3}, {%4,%5,%6,%7}, {%8,%9}, {%0,%1,%2,%3};"
        : "+f"(c[0]), "+f"(c[1]), "+f"(c[2]), "+f"(c[3])
        : "r"(a[0]), "r"(a[1]), "r"(a[2]), "r"(a[3]),
          "r"(b[0]), "r"(b[1]));
}
// swizzled byte offset: row r (64-half rows = 8 x 16B units), unit u
__device__ __forceinline__ uint32_t swz(int r, int u) {
    return (uint32_t)(((r << 3) + (u ^ (r & 7))) << 4);
}

// ---------------- weight transpose: dst[n,r] = half(src[r,n]) ----------------
__global__ void __launch_bounds__(256) transpose_kernel(
    const float* __restrict__ src, __half* __restrict__ dst, int R, int Ncols) {
    __shared__ float t[32][33];
    int bx = blockIdx.x * 32, by = blockIdx.y * 32;
    int tx = threadIdx.x, ty = threadIdx.y;
#pragma unroll
    for (int i = 0; i < 32; i += 8)
        t[ty + i][tx] = src[(size_t)(by + ty + i) * Ncols + bx + tx];
    __syncthreads();
#pragma unroll
    for (int i = 0; i < 32; i += 8)
        dst[(size_t)(bx + ty + i) * R + by + tx] = __float2half(t[tx][ty + i]);
}

// ---------------- concat QKV bias -------------------------------------------
__global__ void concat_bias(const float* __restrict__ a,
                            const float* __restrict__ b,
                            const float* __restrict__ c,
                            float* __restrict__ o) {
    int t = blockIdx.x * 256 + threadIdx.x;
    if (t < CC)            o[t] = a[t];
    else if (t < 2 * CC)   o[t] = b[t - CC];
    else if (t < 3 * CC)   o[t] = c[t - 2 * CC];
}

// ---------------- LayerNorm (fp32 in, fp16 out) ------------------------------
__global__ void __launch_bounds__(256) ln_kernel(
    const float* __restrict__ X, const float* __restrict__ gw,
    const float* __restrict__ gb, __half* __restrict__ O) {
    __shared__ float red[16];
    int row = blockIdx.x;
    int t = threadIdx.x;
    const float* xr = X + (size_t)row * CC;
    float4 v = *(const float4*)(xr + t * 4);
    float s  = v.x + v.y + v.z + v.w;
    float ss = v.x*v.x + v.y*v.y + v.z*v.z + v.w*v.w;
#pragma unroll
    for (int o = 16; o; o >>= 1) {
        s  += __shfl_down_sync(0xffffffffu, s,  o);
        ss += __shfl_down_sync(0xffffffffu, ss, o);
    }
    if ((t & 31) == 0) { red[t >> 5] = s; red[8 + (t >> 5)] = ss; }
    __syncthreads();
    if (t == 0) {
        float a = 0.f, c = 0.f;
#pragma unroll
        for (int i = 0; i < 8; i++) { a += red[i]; c += red[8 + i]; }
        float mean = a * (1.f / CC);
        float var  = c * (1.f / CC) - mean * mean;
        red[0] = mean;
        red[1] = rsqrtf(var + 1e-5f);
    }
    __syncthreads();
    float mean = red[0], rstd = red[1];
    float4 w4 = *(const float4*)(gw + t * 4);
    float4 b4 = *(const float4*)(gb + t * 4);
    __half2* op = (__half2*)(O + (size_t)row * CC);
    op[t * 2 + 0] = __floats2half2_rn((v.x - mean) * rstd * w4.x + b4.x,
                                      (v.y - mean) * rstd * w4.y + b4.y);
    op[t * 2 + 1] = __floats2half2_rn((v.z - mean) * rstd * w4.z + b4.z,
                                      (v.w - mean) * rstd * w4.w + b4.w);
}

// ---------------- fp16 mma GEMM: tile 128x128, BK=64, 3-stage pipeline -------
// A: [M,K] fp16 row-major.  Bt: [N,K] fp16 row-major.
// EPI: 0 = bias -> fp16 out, 1 = bias+relu -> fp16 out, 2 = bias+residual -> fp32 out
#define GSMEM_BYTES (3 * 32768)   // 3 stages x (A 16KB + B 16KB)

template <int EPI>
__global__ void __launch_bounds__(256, 2) gemm_h(
    const __half* __restrict__ A, const __half* __restrict__ Bt,
    const float* __restrict__ bias, const float* __restrict__ res,
    void* __restrict__ Cout_, int M, int N, int K) {
    extern __shared__ char smc[];
    int tid = threadIdx.x, wid = tid >> 5, lane = tid & 31;
    int gid = lane >> 2, tig = lane & 3;
    int wm = wid >> 1, wn = wid & 1;
    int bm = blockIdx.y << 7, bn = blockIdx.x << 7;

    const __half* Ag = A  + (size_t)bm * K;
    const __half* Bg = Bt + (size_t)bn * K;
    uint32_t smb = smem_u32(smc);

    auto load_chunk = [&](int c, int b) {
        const __half* Ac = Ag + c * 64;
        const __half* Bc = Bg + c * 64;
        uint32_t ab = smb + b * 32768;
        uint32_t bb = ab + 16384;
#pragma unroll
        for (int i = 0; i < 4; i++) {
            int idx = tid + (i << 8);
            int row = idx >> 3, u = idx & 7;
            uint32_t off = swz(row, u);
            cp16(ab + off, Ac + (size_t)row * K + (u << 3));
            cp16(bb + off, Bc + (size_t)row * K + (u << 3));
        }
    };

    float acc[2][8][4];
#pragma unroll
    for (int mt = 0; mt < 2; mt++)
#pragma unroll
        for (int nt = 0; nt < 8; nt++)
#pragma unroll
            for (int r = 0; r < 4; r++) acc[mt][nt][r] = 0.f;

    const int l15 = lane & 15, l7 = lane & 7;
    const int aU = lane >> 4;              // A/Q unit add
    const int bR = (lane >> 4) << 3;       // B row add
    const int bU = (lane >> 3) & 1;        // B unit add

    int nc = K >> 6;
    load_chunk(0, 0);
    CP_COMMIT();
    if (nc > 1) { load_chunk(1, 1); CP_COMMIT(); }

    for (int c = 0; c < nc; c++) {
        if (c + 1 < nc) CP_WAIT1(); else CP_WAIT0();
        __syncthreads();
        if (c + 2 < nc) {   // writes buffer consumed at chunk c-1: safe post-barrier
            int nb = (c + 2) % 3;
            load_chunk(c + 2, nb);
            CP_COMMIT();
        }
        uint32_t sA = smb + (c % 3) * 32768;
        uint32_t sB = sA + 16384;
#pragma unroll
        for (int ks = 0; ks < 4; ks++) {
            uint32_t aF[2][4], bF[8][2];
#pragma unroll
            for (int mt = 0; mt < 2; mt++) {
                int r = wm * 32 + mt * 16 + l15;
                ldsm4(aF[mt], sA + swz(r, 2 * ks + aU));
            }
#pragma unroll
            for (int ntp = 0; ntp < 4; ntp++) {
                int r = wn * 64 + ntp * 16 + l7 + bR;
                uint32_t t4[4];
                ldsm4(t4, sB + swz(r, 2 * ks + bU));
                bF[2 * ntp][0] = t4[0]; bF[2 * ntp][1] = t4[1];
                bF[2 * ntp + 1][0] = t4[2]; bF[2 * ntp + 1][1] = t4[3];
            }
#pragma unroll
            for (int mt = 0; mt < 2; mt++)
#pragma unroll
                for (int nt = 0; nt < 8; nt++)
                    mma_f16(acc[mt][nt], aF[mt], bF[nt]);
        }
    }

    // ---- epilogue ----
#pragma unroll
    for (int mt = 0; mt < 2; mt++) {
        int r0 = bm + wm * 32 + mt * 16 + gid;
#pragma unroll
        for (int half = 0; half < 2; half++) {
            int row = r0 + half * 8;
#pragma unroll
            for (int nt = 0; nt < 8; nt++) {
                int col = bn + wn * 64 + nt * 8 + tig * 2;
                float2 bv = *(const float2*)(bias + col);
                float ox = acc[mt][nt][half * 2 + 0] + bv.x;
                float oy = acc[mt][nt][half * 2 + 1] + bv.y;
                if (EPI == 1) { ox = fmaxf(ox, 0.f); oy = fmaxf(oy, 0.f); }
                if (EPI == 2) {
                    float2 rr = *(const float2*)(res + (size_t)row * N + col);
                    float* Co = (float*)Cout_;
                    *(float2*)(Co + (size_t)row * N + col) =
                        make_float2(ox + rr.x, oy + rr.y);
                } else {
                    __half* Co = (__half*)Cout_;
                    *(__half2*)(Co + (size_t)row * N + col) =
                        __floats2half2_rn(ox, oy);
                }
            }
        }
    }
}

// ---------------- fp16 flash attention: BQ=128, BK=64, 3-buffer KV ring -----
// smem: sQ 16KB | sK 3x8KB | sV 3x8KB | sP 16KB  = 80KB
#define AS_Q 0
#define AS_K 16384
#define AS_V 40960
#define AS_P 65536
#define ASMEM_BYTES 81920

__global__ void __launch_bounds__(256) attn_h(
    const __half* __restrict__ QKV, __half* __restrict__ Y) {
    extern __shared__ char smc[];
    uint32_t smb = smem_u32(smc);
    int qt = blockIdx.x, hh = blockIdx.y, b = blockIdx.z;
    int tid = threadIdx.x, wid = tid >> 5, lane = tid & 31;
    int gid = lane >> 2, tig = lane & 3;
    int q0 = qt * 128;

    const __half* Qg = QKV + (size_t)b * TT * C3 + hh * DD;
    const __half* Kg = Qg + CC;
    const __half* Vg = Qg + 2 * CC;

    const int l15 = lane & 15, l7 = lane & 7;
    const int aU = lane >> 4;
    const int bR = (lane >> 4) << 3;
    const int bU = (lane >> 3) & 1;

    auto loadKV = [&](int t, int bf) {
        const __half* Kt = Kg + (size_t)(t * 64) * C3;
        const __half* Vt = Vg + (size_t)(t * 64) * C3;
        uint32_t dk = smb + AS_K + bf * 8192;
        uint32_t dv = smb + AS_V + bf * 8192;
#pragma unroll
        for (int i = 0; i < 2; i++) {
            int idx = tid + (i << 8);
            int row = idx >> 3, u = idx & 7;
            uint32_t off = swz(row, u);
            cp16(dk + off, Kt + (size_t)row * C3 + (u << 3));
            cp16(dv + off, Vt + (size_t)row * C3 + (u << 3));
        }
    };

    int ntiles = 2 * qt + 2;
    // group 0: Q tile + KV0
#pragma unroll
    for (int i = 0; i < 4; i++) {
        int idx = tid + (i << 8);
        int row = idx >> 3, u = idx & 7;
        cp16(smb + AS_Q + swz(row, u), Qg + (size_t)(q0 + row) * C3 + (u << 3));
    }
    loadKV(0, 0);
    CP_COMMIT();
    loadKV(1, 1);
    CP_COMMIT();
    CP_WAIT1();          // Q + KV0 complete
    __syncthreads();

    // ---- Q fragments ----
    uint32_t qf[4][4];
#pragma unroll
    for (int ks = 0; ks < 4; ks++) {
        int r = wid * 16 + l15;
        ldsm4(qf[ks], smb + AS_Q + swz(r, 2 * ks + aU));
    }

    float m_i[2] = {-1e30f, -1e30f}, l_i[2] = {0.f, 0.f};
    float oacc[8][4];
#pragma unroll
    for (int nt = 0; nt < 8; nt++)
#pragma unroll
        for (int r = 0; r < 4; r++) oacc[nt][r] = 0.f;

    const int rbase = q0 + wid * 16 + gid;

    for (int t = 0; t < ntiles; t++) {
        if (t > 0) {
            if (t + 1 < ntiles) CP_WAIT1(); else CP_WAIT0();
            __syncthreads();
        }
        if (t + 2 < ntiles) {   // buffer (t+2)%3 consumed at tile t-1: safe
            loadKV(t + 2, (t + 2) % 3);
            CP_COMMIT();
        }
        int k0t = t * 64;
        bool active = (k0t <= q0 + wid * 16 + 15);
        if (active) {
            int bf = t % 3;
            uint32_t sK = smb + AS_K + bf * 8192;
            uint32_t sV = smb + AS_V + bf * 8192;
            // ---- S = Q @ K^T ----
            float sfr[8][4];
#pragma unroll
            for (int nt = 0; nt < 8; nt++)
#pragma unroll
                for (int r = 0; r < 4; r++) sfr[nt][r] = 0.f;
#pragma unroll
            for (int ks = 0; ks < 4; ks++) {
                uint32_t bF[8][2];
#pragma unroll
                for (int ntp = 0; ntp < 4; ntp++) {
                    int r = ntp * 16 + l7 + bR;
                    uint32_t t4[4];
                    ldsm4(t4, sK + swz(r, 2 * ks + bU));
                    bF[2 * ntp][0] = t4[0]; bF[2 * ntp][1] = t4[1];
                    bF[2 * ntp + 1][0] = t4[2]; bF[2 * ntp + 1][1] = t4[3];
                }
#pragma unroll
                for (int nt = 0; nt < 8; nt++)
                    mma_f16(sfr[nt], qf[ks], bF[nt]);
            }
            // ---- scale + causal mask ----
#pragma unroll
            for (int nt = 0; nt < 8; nt++)
#pragma unroll
                for (int r = 0; r < 4; r++) sfr[nt][r] *= 0.125f;
            if (k0t + 63 > rbase) {
#pragma unroll
                for (int nt = 0; nt < 8; nt++) {
                    int cb = k0t + nt * 8 + tig * 2;
                    if (cb     > rbase)     sfr[nt][0] = -1e30f;
                    if (cb + 1 > rbase)     sfr[nt][1] = -1e30f;
                    if (cb     > rbase + 8) sfr[nt][2] = -1e30f;
                    if (cb + 1 > rbase + 8) sfr[nt][3] = -1e30f;
                }
            }
            // ---- online softmax; write P (fp16) to per-warp smem ----
#pragma unroll
            for (int h = 0; h < 2; h++) {
                float rm = -1e30f;
#pragma unroll
                for (int nt = 0; nt < 8; nt++)
                    rm = fmaxf(rm, fmaxf(sfr[nt][2 * h], sfr[nt][2 * h + 1]));
                rm = fmaxf(rm, __shfl_xor_sync(0xffffffffu, rm, 1));
                rm = fmaxf(rm, __shfl_xor_sync(0xffffffffu, rm, 2));
                float mn = fmaxf(m_i[h], rm);
                float alpha = __expf(m_i[h] - mn);
                m_i[h] = mn;
                float rs = 0.f;
                int pr = wid * 16 + gid + h * 8;
#pragma unroll
                for (int nt = 0; nt < 8; nt++) {
                    float p0 = __expf(sfr[nt][2 * h]     - mn);
                    float p1 = __expf(sfr[nt][2 * h + 1] - mn);
                    rs += p0 + p1;
                    int col = nt * 8 + tig * 2;
                    *(__half2*)(smc + AS_P + swz(pr, col >> 3) + (col & 7) * 2) =
                        __floats2half2_rn(p0, p1);
                    oacc[nt][2 * h]     *= alpha;
                    oacc[nt][2 * h + 1] *= alpha;
                }
                rs += __shfl_xor_sync(0xffffffffu, rs, 1);
                rs += __shfl_xor_sync(0xffffffffu, rs, 2);
                l_i[h] = l_i[h] * alpha + rs;
            }
            __syncwarp();
            // ---- O += P @ V  (V via ldmatrix.trans) ----
#pragma unroll
            for (int ks = 0; ks < 4; ks++) {
                uint32_t pf[4];
                {
                    int r = wid * 16 + l15;
                    ldsm4(pf, smb + AS_P + swz(r, 2 * ks + aU));
                }
#pragma unroll
                for (int ntp = 0; ntp < 4; ntp++) {
                    int kk = ks * 16 + l7 + ((lane >> 3) & 1) * 8;
                    uint32_t t4[4];
                    ldsm4t(t4, sV + swz(kk, 2 * ntp + aU));
                    mma_f16(oacc[2 * ntp],     pf, t4);
                    mma_f16(oacc[2 * ntp + 1], pf, t4 + 2);
                }
            }
        }
    }

    // ---- output (fp16, feeds Wo GEMM) ----
    __half* Yg = Y + (size_t)b * TT * CC + hh * DD;
#pragma unroll
    for (int h = 0; h < 2; h++) {
        float inv = 1.f / l_i[h];
        __half* yr = Yg + (size_t)(rbase + h * 8) * CC;
#pragma unroll
        for (int nt = 0; nt < 8; nt++) {
            int col = nt * 8 + tig * 2;
            *(__half2*)(yr + col) = __floats2half2_rn(
                oacc[nt][2 * h] * inv, oacc[nt][2 * h + 1] * inv);
        }
    }
}

// ---------------- launch ---------------------------------------------------
extern "C" void kernel_launch(void* const* d_in, const int* in_sizes, int n_in,
                              void* d_out, int out_size) {
    const float* x    = (const float*)d_in[0];
    const float* ln1w = (const float*)d_in[1];
    const float* ln1b = (const float*)d_in[2];
    const float* Wq   = (const float*)d_in[3];
    const float* bq   = (const float*)d_in[4];
    const float* Wk   = (const float*)d_in[5];
    const float* bk   = (const float*)d_in[6];
    const float* Wv   = (const float*)d_in[7];
    const float* bv   = (const float*)d_in[8];
    const float* Wo   = (const float*)d_in[9];
    const float* bo   = (const float*)d_in[10];
    const float* ln2w = (const float*)d_in[11];
    const float* ln2b = (const float*)d_in[12];
    const float* W1   = (const float*)d_in[13];
    const float* b1   = (const float*)d_in[14];
    const float* W2   = (const float*)d_in[15];
    const float* b2   = (const float*)d_in[16];
    float* out = (float*)d_out;

    __half *h, *qkv, *y, *ff, *wT;
    float *x2, *bqkv;
    cudaGetSymbolAddress((void**)&h,    g_h);
    cudaGetSymbolAddress((void**)&qkv,  g_qkv);
    cudaGetSymbolAddress((void**)&y,    g_y);
    cudaGetSymbolAddress((void**)&x2,   g_x2);
    cudaGetSymbolAddress((void**)&ff,   g_ff);
    cudaGetSymbolAddress((void**)&wT,   g_wT);
    cudaGetSymbolAddress((void**)&bqkv, g_bqkv);

    __half* WqkvT = wT;                                  // [3C, C]
    __half* WoT   = WqkvT + (size_t)3 * CC * CC;         // [C, C]
    __half* W1T   = WoT + (size_t)CC * CC;               // [WFF, C]
    __half* W2T   = W1T + (size_t)CC * WFF;              // [C, WFF]

    cudaFuncSetAttribute(attn_h,
                         cudaFuncAttributeMaxDynamicSharedMemorySize, ASMEM_BYTES);
    cudaFuncSetAttribute(gemm_h<0>,
                         cudaFuncAttributeMaxDynamicSharedMemorySize, GSMEM_BYTES);
    cudaFuncSetAttribute(gemm_h<1>,
                         cudaFuncAttributeMaxDynamicSharedMemorySize, GSMEM_BYTES);
    cudaFuncSetAttribute(gemm_h<2>,
                         cudaFuncAttributeMaxDynamicSharedMemorySize, GSMEM_BYTES);

    // ---- weight transposes (fp32 -> fp16) + bias concat ----
    dim3 tb(32, 8);
    transpose_kernel<<<dim3(CC / 32,  CC / 32),  tb>>>(Wq, WqkvT,                        CC,  CC);
    transpose_kernel<<<dim3(CC / 32,  CC / 32),  tb>>>(Wk, WqkvT + (size_t)CC * CC,      CC,  CC);
    transpose_kernel<<<dim3(CC / 32,  CC / 32),  tb>>>(Wv, WqkvT + (size_t)2 * CC * CC,  CC,  CC);
    transpose_kernel<<<dim3(CC / 32,  CC / 32),  tb>>>(Wo, WoT, CC,  CC);
    transpose_kernel<<<dim3(WFF / 32, CC / 32),  tb>>>(W1, W1T, CC,  WFF);
    transpose_kernel<<<dim3(CC / 32,  WFF / 32), tb>>>(W2, W2T, WFF, CC);
    concat_bias<<<12, 256>>>(bq, bk, bv, bqkv);

    // LN1
    ln_kernel<<<MM, 256>>>(x, ln1w, ln1b, h);
    // fused QKV projection (N = 3072)
    gemm_h<0><<<dim3(C3 / 128, MM / 128), 256, GSMEM_BYTES>>>(
        h, WqkvT, bqkv, nullptr, qkv, MM, C3, CC);
    // causal attention
    attn_h<<<dim3(TT / 128, HH, BB), 256, ASMEM_BYTES>>>(qkv, y);
    // output projection + residual
    dim3 g1(CC / 128, MM / 128);
    gemm_h<2><<<g1, 256, GSMEM_BYTES>>>(y, WoT, bo, x, x2, MM, CC, CC);
    // LN2
    ln_kernel<<<MM, 256>>>(x2, ln2w, ln2b, h);
    // FF1 (relu)
    gemm_h<1><<<dim3(WFF / 128, MM / 128), 256, GSMEM_BYTES>>>(
        h, W1T, b1, nullptr, ff, MM, WFF, CC);
    // FF2 + residual -> out
    gemm_h<2><<<g1, 256, GSMEM_BYTES>>>(ff, W2T, b2, x2, out, MM, CC, WFF);
}